// round 2
// baseline (speedup 1.0000x reference)
#include <cuda_runtime.h>
#include <math.h>

#define VOCAB   100
#define NBOND   4
#define EMB     128
#define N_NODES 25000
#define N_EDGES 50000
#define MAX_NB  6
#define HOFF    104       // IN_DIM = VOCAB + NBOND; h-part rows of W start here
#define TE      10        // edges per block in depth kernel (keeps smem < 48KB static)
#define TPG     5         // edges per 128-thread group (TE/2)

// ping-pong hidden/cell state buffers (static device scratch; no allocation)
__device__ float g_h[2][N_EDGES * EMB];
__device__ float g_c[2][N_EDGES * EMB];

__device__ __forceinline__ float sigf(float x) {
    return 1.0f / (1.0f + __expf(-x));
}

// ---------------------------------------------------------------------------
// Depth 0: h = c = 0 entering, so no GEMM at all. Per (e,d):
//   i = sig(Wi[nid]+Wi[100+et]+bi), o = sig(...), u = tanh(...)
//   c = i*u ; h = o*tanh(c) ; edge 0 masked to zero.
// ---------------------------------------------------------------------------
__global__ __launch_bounds__(256) void k_depth0(
    const int* __restrict__ node_ids, const int* __restrict__ edge_src,
    const int* __restrict__ edge_type,
    const float* __restrict__ Wi, const float* __restrict__ bi,
    const float* __restrict__ Wo, const float* __restrict__ bo,
    const float* __restrict__ Wu, const float* __restrict__ bu)
{
    int idx = blockIdx.x * blockDim.x + threadIdx.x;   // e*128 + d
    int e = idx >> 7, d = idx & 127;
    int nrow = node_ids[edge_src[e]];
    int brow = VOCAB + edge_type[e];
    float pi = Wi[nrow * EMB + d] + Wi[brow * EMB + d] + bi[d];
    float po = Wo[nrow * EMB + d] + Wo[brow * EMB + d] + bo[d];
    float pu = Wu[nrow * EMB + d] + Wu[brow * EMB + d] + bu[d];
    float i = sigf(pi), o = sigf(po), u = tanhf(pu);
    float c = i * u;
    float h = o * tanhf(c);
    if (e == 0) { h = 0.0f; c = 0.0f; }
    g_h[0][idx] = h;
    g_c[0][idx] = c;
}

// ---------------------------------------------------------------------------
// Generic depth step (depths 1..3).
// Block: TE=10 edges, 256 threads = 2 edge-groups x 128 dims, TPG=5 edges/group.
// Static smem (~36 KB): gathered neighbor h rows + per-edge neighbor sums + indices.
// ---------------------------------------------------------------------------
__global__ __launch_bounds__(256) void k_depth(
    int cur, int nxt,
    const int* __restrict__ node_ids, const int* __restrict__ edge_src,
    const int* __restrict__ edge_type, const int* __restrict__ bond_list,
    const float* __restrict__ Wi, const float* __restrict__ bi,
    const float* __restrict__ Wo, const float* __restrict__ bo,
    const float* __restrict__ Wf, const float* __restrict__ bf,
    const float* __restrict__ Wu, const float* __restrict__ bu)
{
    __shared__ float s_h[TE * MAX_NB * EMB];    // 30720 B
    __shared__ float s_hsum[TE * EMB];          //  5120 B
    __shared__ int   s_b[TE * MAX_NB];          //   240 B
    __shared__ int   s_nrow[TE];
    __shared__ int   s_brow[TE];

    const float* __restrict__ h_old = g_h[cur];
    const float* __restrict__ c_old = g_c[cur];
    float* __restrict__ h_new = g_h[nxt];
    float* __restrict__ c_new = g_c[nxt];

    const int tid = threadIdx.x;
    const int e0  = blockIdx.x * TE;

    // --- metadata loads ---
    if (tid < TE * MAX_NB) {
        s_b[tid] = bond_list[e0 * MAX_NB + tid];
    } else if (tid < TE * MAX_NB + TE) {
        int e = tid - TE * MAX_NB;
        s_nrow[e] = node_ids[edge_src[e0 + e]];
    } else if (tid < TE * MAX_NB + 2 * TE) {
        int e = tid - TE * MAX_NB - TE;
        s_brow[e] = VOCAB + edge_type[e0 + e];
    }
    __syncthreads();

    // --- gather neighbor h rows into smem (coalesced 512B rows) ---
    #pragma unroll 4
    for (int idx = tid; idx < TE * MAX_NB * EMB; idx += 256) {
        int r = idx >> 7;          // e*6 + k
        int dd = idx & 127;
        s_h[idx] = h_old[s_b[r] * EMB + dd];
    }
    __syncthreads();

    const int d  = tid & 127;
    const int eg = tid >> 7;       // 0 or 1 -> edges [eg*TPG, eg*TPG+TPG)

    // --- per-edge neighbor sum ---
    #pragma unroll
    for (int t = 0; t < TPG; t++) {
        int e = eg * TPG + t;
        float s = 0.0f;
        #pragma unroll
        for (int k = 0; k < MAX_NB; k++)
            s += s_h[(e * MAX_NB + k) * EMB + d];
        s_hsum[e * EMB + d] = s;
    }
    __syncthreads();

    // --- phase 1: i/o/u gates:  acc = h_sum @ W_h (column d) ---
    const float* WiH = Wi + HOFF * EMB + d;
    const float* WoH = Wo + HOFF * EMB + d;
    const float* WuH = Wu + HOFF * EMB + d;

    float acc_i[TPG], acc_o[TPG], acc_u[TPG];
    #pragma unroll
    for (int t = 0; t < TPG; t++) { acc_i[t] = 0.f; acc_o[t] = 0.f; acc_u[t] = 0.f; }

    for (int j = 0; j < EMB; j += 4) {
        float wi[4], wo[4], wu[4];
        #pragma unroll
        for (int q = 0; q < 4; q++) {
            wi[q] = WiH[(j + q) * EMB];
            wo[q] = WoH[(j + q) * EMB];
            wu[q] = WuH[(j + q) * EMB];
        }
        #pragma unroll
        for (int t = 0; t < TPG; t++) {
            float4 hs = *(const float4*)&s_hsum[(eg * TPG + t) * EMB + j];
            acc_i[t] += hs.x * wi[0] + hs.y * wi[1] + hs.z * wi[2] + hs.w * wi[3];
            acc_o[t] += hs.x * wo[0] + hs.y * wo[1] + hs.z * wo[2] + hs.w * wo[3];
            acc_u[t] += hs.x * wu[0] + hs.y * wu[1] + hs.z * wu[2] + hs.w * wu[3];
        }
    }

    // activate; keep o and start c accumulator with i*u
    float o_g[TPG], c_acc[TPG], pre_f[TPG];
    const float bi_d = bi[d], bo_d = bo[d], bu_d = bu[d], bf_d = bf[d];
    #pragma unroll
    for (int t = 0; t < TPG; t++) {
        int e = eg * TPG + t;
        int nr = s_nrow[e], br = s_brow[e];
        float i_g = sigf(acc_i[t] + Wi[nr * EMB + d] + Wi[br * EMB + d] + bi_d);
        o_g[t]    = sigf(acc_o[t] + Wo[nr * EMB + d] + Wo[br * EMB + d] + bo_d);
        float u_g = tanhf(acc_u[t] + Wu[nr * EMB + d] + Wu[br * EMB + d] + bu_d);
        c_acc[t]  = i_g * u_g;
        pre_f[t]  = Wf[nr * EMB + d] + Wf[br * EMB + d] + bf_d;   // fmess part of f, shared over k
    }

    // --- phase 2: forget gates per neighbor + cell accumulation ---
    const float* WfH = Wf + HOFF * EMB + d;
    for (int k = 0; k < MAX_NB; k++) {
        float acc_f[TPG];
        #pragma unroll
        for (int t = 0; t < TPG; t++) acc_f[t] = 0.f;

        for (int j = 0; j < EMB; j += 4) {
            float wf[4];
            #pragma unroll
            for (int q = 0; q < 4; q++) wf[q] = WfH[(j + q) * EMB];
            #pragma unroll
            for (int t = 0; t < TPG; t++) {
                float4 hv = *(const float4*)&s_h[((eg * TPG + t) * MAX_NB + k) * EMB + j];
                acc_f[t] += hv.x * wf[0] + hv.y * wf[1] + hv.z * wf[2] + hv.w * wf[3];
            }
        }
        #pragma unroll
        for (int t = 0; t < TPG; t++) {
            int e = eg * TPG + t;
            float f = sigf(acc_f[t] + pre_f[t]);
            int b = s_b[e * MAX_NB + k];
            c_acc[t] += f * c_old[b * EMB + d];
        }
    }

    // --- epilogue ---
    #pragma unroll
    for (int t = 0; t < TPG; t++) {
        int ge = e0 + eg * TPG + t;
        float c = c_acc[t];
        float h = o_g[t] * tanhf(c);
        if (ge == 0) { h = 0.0f; c = 0.0f; }
        h_new[ge * EMB + d] = h;
        c_new[ge * EMB + d] = c;
    }
}

// ---------------------------------------------------------------------------
// Final: nei_msg = sum_k h[adj[n,k]];  out = relu(Wt[nid] + bt + msg @ Wt_h)
// ---------------------------------------------------------------------------
__global__ __launch_bounds__(256) void k_final(
    const int* __restrict__ node_ids, const int* __restrict__ adj_list,
    const float* __restrict__ Wt, const float* __restrict__ bt,
    float* __restrict__ out)
{
    __shared__ float s_msg[16][EMB];
    __shared__ int   s_nid[16];

    const int tid = threadIdx.x;
    const int n0  = blockIdx.x * 16;
    const float* __restrict__ h = g_h[1];   // after depths 0..3: final state in buffer 1

    if (tid < 16) {
        int n = n0 + tid;
        s_nid[tid] = (n < N_NODES) ? node_ids[n] : 0;
    }

    const int d  = tid & 127;
    const int eg = tid >> 7;

    #pragma unroll
    for (int t = 0; t < 8; t++) {
        int n = n0 + eg * 8 + t;
        float s = 0.0f;
        if (n < N_NODES) {
            #pragma unroll
            for (int k = 0; k < MAX_NB; k++)
                s += h[adj_list[n * MAX_NB + k] * EMB + d];
        }
        s_msg[eg * 8 + t][d] = s;
    }
    __syncthreads();

    const float* WtH = Wt + VOCAB * EMB + d;
    float acc[8];
    #pragma unroll
    for (int t = 0; t < 8; t++) acc[t] = 0.f;

    for (int j = 0; j < EMB; j += 4) {
        float wt[4];
        #pragma unroll
        for (int q = 0; q < 4; q++) wt[q] = WtH[(j + q) * EMB];
        #pragma unroll
        for (int t = 0; t < 8; t++) {
            float4 m = *(const float4*)&s_msg[eg * 8 + t][j];
            acc[t] += m.x * wt[0] + m.y * wt[1] + m.z * wt[2] + m.w * wt[3];
        }
    }

    const float bt_d = bt[d];
    #pragma unroll
    for (int t = 0; t < 8; t++) {
        int n = n0 + eg * 8 + t;
        if (n < N_NODES) {
            float v = acc[t] + Wt[s_nid[eg * 8 + t] * EMB + d] + bt_d;
            v = fmaxf(v, 0.0f);
            if (n == 0) v = 0.0f;
            out[n * EMB + d] = v;
        }
    }
}

// ---------------------------------------------------------------------------
extern "C" void kernel_launch(void* const* d_in, const int* in_sizes, int n_in,
                              void* d_out, int out_size)
{
    const int*   node_ids  = (const int*)d_in[0];
    const int*   edge_src  = (const int*)d_in[1];
    const int*   edge_type = (const int*)d_in[2];
    const int*   adj_list  = (const int*)d_in[3];
    const int*   bond_list = (const int*)d_in[4];
    const float* Wi = (const float*)d_in[5];
    const float* bi = (const float*)d_in[6];
    const float* Wo = (const float*)d_in[7];
    const float* bo = (const float*)d_in[8];
    const float* Wf = (const float*)d_in[9];
    const float* bf = (const float*)d_in[10];
    const float* Wu = (const float*)d_in[11];
    const float* bu = (const float*)d_in[12];
    const float* Wt = (const float*)d_in[13];
    const float* bt = (const float*)d_in[14];
    float* out = (float*)d_out;

    k_depth0<<<(N_EDGES * EMB) / 256, 256>>>(node_ids, edge_src, edge_type,
                                             Wi, bi, Wo, bo, Wu, bu);

    const int nblk = N_EDGES / TE;   // 5000
    k_depth<<<nblk, 256>>>(0, 1, node_ids, edge_src, edge_type, bond_list,
                           Wi, bi, Wo, bo, Wf, bf, Wu, bu);
    k_depth<<<nblk, 256>>>(1, 0, node_ids, edge_src, edge_type, bond_list,
                           Wi, bi, Wo, bo, Wf, bf, Wu, bu);
    k_depth<<<nblk, 256>>>(0, 1, node_ids, edge_src, edge_type, bond_list,
                           Wi, bi, Wo, bo, Wf, bf, Wu, bu);

    k_final<<<(N_NODES + 15) / 16, 256>>>(node_ids, adj_list, Wt, bt, out);
}

// round 3
// speedup vs baseline: 1.9153x; 1.9153x over previous
#include <cuda_runtime.h>
#include <math.h>

#define VOCAB   100
#define NBOND   4
#define EMB     128
#define N_NODES 25000
#define N_EDGES 50000
#define MAX_NB  6
#define HOFF    104       // IN_DIM = VOCAB + NBOND

// ping-pong hidden/cell state + per-gate GEMM outputs (static device scratch)
__device__ float g_h[2][N_EDGES * EMB];
__device__ float g_c[2][N_EDGES * EMB];
__device__ float g_H[4][N_EDGES * EMB];   // Hi, Ho, Hu, Hf (g_H[0] reused for Ht)

__device__ __forceinline__ float sigf(float x) {
    return 1.0f / (1.0f + __expf(-x));
}

// ---------------------------------------------------------------------------
// Depth 0: entering h=c=0 -> pure one-hot row gather + activations.
// ---------------------------------------------------------------------------
__global__ __launch_bounds__(256) void k_depth0(
    const int* __restrict__ node_ids, const int* __restrict__ edge_src,
    const int* __restrict__ edge_type,
    const float* __restrict__ Wi, const float* __restrict__ bi,
    const float* __restrict__ Wo, const float* __restrict__ bo,
    const float* __restrict__ Wu, const float* __restrict__ bu)
{
    int idx = blockIdx.x * blockDim.x + threadIdx.x;   // e*128 + d
    int e = idx >> 7, d = idx & 127;
    int nrow = node_ids[edge_src[e]];
    int brow = VOCAB + edge_type[e];
    float pi = Wi[nrow * EMB + d] + Wi[brow * EMB + d] + bi[d];
    float po = Wo[nrow * EMB + d] + Wo[brow * EMB + d] + bo[d];
    float pu = Wu[nrow * EMB + d] + Wu[brow * EMB + d] + bu[d];
    float i = sigf(pi), o = sigf(po), u = tanhf(pu);
    float c = i * u;
    float h = o * tanhf(c);
    if (e == 0) { h = 0.0f; c = 0.0f; }
    g_h[0][idx] = h;
    g_c[0][idx] = c;
}

// ---------------------------------------------------------------------------
// Dense GEMM: g_H[blockIdx.y] = g_h[cur] @ W_h  where W_h = W(+row offset).
// C tile 64 edges x 128 dims per block; 256 threads; each thread 8e x 4d.
// A tile staged in smem [64][136] (padded rows, LDS broadcast in mainloop).
// W pointers are pre-offset to the h-part rows (HOFF or VOCAB).
// ---------------------------------------------------------------------------
__global__ __launch_bounds__(256) void k_gemm(
    int cur,
    const float* __restrict__ W0, const float* __restrict__ W1,
    const float* __restrict__ W2, const float* __restrict__ W3)
{
    __shared__ float A_s[64][136];

    const float* __restrict__ A = g_h[cur];
    const float* __restrict__ W;
    float* __restrict__ H = g_H[blockIdx.y];
    switch (blockIdx.y) {
        case 0: W = W0; break;
        case 1: W = W1; break;
        case 2: W = W2; break;
        default: W = W3; break;
    }

    const int tid = threadIdx.x;
    const int e0  = blockIdx.x * 64;

    // stage A tile (h rows) into smem; zero-fill OOB rows of last block
    {
        int kq = tid & 31;        // float4 index within row (128/4)
        int ew = tid >> 5;        // 0..7
        #pragma unroll
        for (int it = 0; it < 8; it++) {
            int e = ew + it * 8;
            float4 v = make_float4(0.f, 0.f, 0.f, 0.f);
            if (e0 + e < N_EDGES)
                v = ((const float4*)A)[(e0 + e) * 32 + kq];
            *(float4*)&A_s[e][4 * kq] = v;
        }
    }
    __syncthreads();

    const int dl = tid & 31;
    const int d0 = 4 * dl;            // this thread's 4 output dims
    const int er = (tid >> 5) * 8;    // this thread's 8 edge rows

    float4 acc[8];
    #pragma unroll
    for (int t = 0; t < 8; t++) acc[t] = make_float4(0.f, 0.f, 0.f, 0.f);

    #pragma unroll 2
    for (int k4 = 0; k4 < 32; k4++) {
        const float* Wk = W + (4 * k4) * EMB + d0;
        float4 b0 = *(const float4*)(Wk + 0 * EMB);
        float4 b1 = *(const float4*)(Wk + 1 * EMB);
        float4 b2 = *(const float4*)(Wk + 2 * EMB);
        float4 b3 = *(const float4*)(Wk + 3 * EMB);
        #pragma unroll
        for (int t = 0; t < 8; t++) {
            float4 a = *(const float4*)&A_s[er + t][4 * k4];
            acc[t].x += a.x * b0.x + a.y * b1.x + a.z * b2.x + a.w * b3.x;
            acc[t].y += a.x * b0.y + a.y * b1.y + a.z * b2.y + a.w * b3.y;
            acc[t].z += a.x * b0.z + a.y * b1.z + a.z * b2.z + a.w * b3.z;
            acc[t].w += a.x * b0.w + a.y * b1.w + a.z * b2.w + a.w * b3.w;
        }
    }

    #pragma unroll
    for (int t = 0; t < 8; t++) {
        int ge = e0 + er + t;
        if (ge < N_EDGES)
            *(float4*)&H[ge * EMB + d0] = acc[t];
    }
}

// ---------------------------------------------------------------------------
// Update: gather per-gate GEMM rows over 6 neighbors + one-hot rows + biases,
// apply LSTM gate math, write next h/c. 2 edges per 256-thread block.
// ---------------------------------------------------------------------------
__global__ __launch_bounds__(256) void k_update(
    int cur, int nxt,
    const int* __restrict__ node_ids, const int* __restrict__ edge_src,
    const int* __restrict__ edge_type, const int* __restrict__ bond_list,
    const float* __restrict__ Wi, const float* __restrict__ bi,
    const float* __restrict__ Wo, const float* __restrict__ bo,
    const float* __restrict__ Wf, const float* __restrict__ bf,
    const float* __restrict__ Wu, const float* __restrict__ bu)
{
    __shared__ int s_b[2 * MAX_NB];
    __shared__ int s_nr[2], s_br[2];

    const float* __restrict__ Hi = g_H[0];
    const float* __restrict__ Ho = g_H[1];
    const float* __restrict__ Hu = g_H[2];
    const float* __restrict__ Hf = g_H[3];
    const float* __restrict__ c_old = g_c[cur];
    float* __restrict__ h_new = g_h[nxt];
    float* __restrict__ c_new = g_c[nxt];

    const int tid = threadIdx.x;
    const int e0  = blockIdx.x * 2;

    if (tid < 2 * MAX_NB) {
        s_b[tid] = bond_list[e0 * MAX_NB + tid];
    } else if (tid < 2 * MAX_NB + 2) {
        int e = tid - 2 * MAX_NB;
        s_nr[e] = node_ids[edge_src[e0 + e]];
    } else if (tid < 2 * MAX_NB + 4) {
        int e = tid - 2 * MAX_NB - 2;
        s_br[e] = VOCAB + edge_type[e0 + e];
    }
    __syncthreads();

    const int le = tid >> 7;         // local edge 0/1
    const int d  = tid & 127;
    const int e  = e0 + le;

    int b[MAX_NB];
    #pragma unroll
    for (int k = 0; k < MAX_NB; k++) b[k] = s_b[le * MAX_NB + k] * EMB + d;

    // batched independent gathers (high MLP)
    float vi[MAX_NB], vo[MAX_NB], vu[MAX_NB], vf[MAX_NB], vc[MAX_NB];
    #pragma unroll
    for (int k = 0; k < MAX_NB; k++) {
        vi[k] = Hi[b[k]];
        vo[k] = Ho[b[k]];
        vu[k] = Hu[b[k]];
        vf[k] = Hf[b[k]];
        vc[k] = c_old[b[k]];
    }

    float si = 0.f, so = 0.f, su = 0.f;
    #pragma unroll
    for (int k = 0; k < MAX_NB; k++) { si += vi[k]; so += vo[k]; su += vu[k]; }

    const int nr = s_nr[le], br = s_br[le];
    float i_g = sigf(si + Wi[nr * EMB + d] + Wi[br * EMB + d] + bi[d]);
    float o_g = sigf(so + Wo[nr * EMB + d] + Wo[br * EMB + d] + bo[d]);
    float u_g = tanhf(su + Wu[nr * EMB + d] + Wu[br * EMB + d] + bu[d]);
    float pre_f = Wf[nr * EMB + d] + Wf[br * EMB + d] + bf[d];

    float c_acc = i_g * u_g;
    #pragma unroll
    for (int k = 0; k < MAX_NB; k++)
        c_acc += sigf(vf[k] + pre_f) * vc[k];

    float h = o_g * tanhf(c_acc);
    if (e == 0) { h = 0.f; c_acc = 0.f; }
    h_new[e * EMB + d] = h;
    c_new[e * EMB + d] = c_acc;
}

// ---------------------------------------------------------------------------
// Final node projection: out = relu(Wt[nid] + bt + sum_k Ht[adj[n,k]]),
// with Ht = h_final @ Wt_h already computed by k_gemm into g_H[0].
// ---------------------------------------------------------------------------
__global__ __launch_bounds__(256) void k_final(
    const int* __restrict__ node_ids, const int* __restrict__ adj_list,
    const float* __restrict__ Wt, const float* __restrict__ bt,
    float* __restrict__ out)
{
    __shared__ int s_a[2 * MAX_NB];
    __shared__ int s_nid[2];

    const float* __restrict__ Ht = g_H[0];

    const int tid = threadIdx.x;
    const int n0  = blockIdx.x * 2;

    if (tid < 2 * MAX_NB) {
        s_a[tid] = adj_list[n0 * MAX_NB + tid];
    } else if (tid < 2 * MAX_NB + 2) {
        int n = tid - 2 * MAX_NB;
        s_nid[n] = node_ids[n0 + n];
    }
    __syncthreads();

    const int ln = tid >> 7;
    const int d  = tid & 127;
    const int n  = n0 + ln;

    float s = 0.f;
    #pragma unroll
    for (int k = 0; k < MAX_NB; k++)
        s += Ht[s_a[ln * MAX_NB + k] * EMB + d];

    float v = s + Wt[s_nid[ln] * EMB + d] + bt[d];
    v = fmaxf(v, 0.f);
    if (n == 0) v = 0.f;
    out[n * EMB + d] = v;
}

// ---------------------------------------------------------------------------
extern "C" void kernel_launch(void* const* d_in, const int* in_sizes, int n_in,
                              void* d_out, int out_size)
{
    const int*   node_ids  = (const int*)d_in[0];
    const int*   edge_src  = (const int*)d_in[1];
    const int*   edge_type = (const int*)d_in[2];
    const int*   adj_list  = (const int*)d_in[3];
    const int*   bond_list = (const int*)d_in[4];
    const float* Wi = (const float*)d_in[5];
    const float* bi = (const float*)d_in[6];
    const float* Wo = (const float*)d_in[7];
    const float* bo = (const float*)d_in[8];
    const float* Wf = (const float*)d_in[9];
    const float* bf = (const float*)d_in[10];
    const float* Wu = (const float*)d_in[11];
    const float* bu = (const float*)d_in[12];
    const float* Wt = (const float*)d_in[13];
    const float* bt = (const float*)d_in[14];
    float* out = (float*)d_out;

    const float* WiH = Wi + HOFF * EMB;
    const float* WoH = Wo + HOFF * EMB;
    const float* WuH = Wu + HOFF * EMB;
    const float* WfH = Wf + HOFF * EMB;
    const float* WtH = Wt + VOCAB * EMB;

    const int GEMM_BLKS = (N_EDGES + 63) / 64;   // 782

    k_depth0<<<(N_EDGES * EMB) / 256, 256>>>(node_ids, edge_src, edge_type,
                                             Wi, bi, Wo, bo, Wu, bu);

    int cur = 0, nxt = 1;
    for (int depth = 1; depth < 4; depth++) {
        k_gemm<<<dim3(GEMM_BLKS, 4), 256>>>(cur, WiH, WoH, WuH, WfH);
        k_update<<<N_EDGES / 2, 256>>>(cur, nxt, node_ids, edge_src, edge_type,
                                       bond_list, Wi, bi, Wo, bo, Wf, bf, Wu, bu);
        int t = cur; cur = nxt; nxt = t;
    }

    // final state in g_h[cur] (= g_h[1] after 3 swaps... cur toggles 0->1->0->1)
    k_gemm<<<dim3(GEMM_BLKS, 1), 256>>>(cur, WtH, WtH, WtH, WtH);
    k_final<<<N_NODES / 2, 256>>>(node_ids, adj_list, Wt, bt, out);
}

// round 6
// speedup vs baseline: 2.7394x; 1.4303x over previous
#include <cuda_runtime.h>
#include <cuda_bf16.h>
#include <math.h>
#include <stdint.h>

#define VOCAB   100
#define NBOND   4
#define EMB     128
#define N_NODES 25000
#define N_EDGES 50000
#define MAX_NB  6
#define HOFF    104
#define NT      391              // ceil(50000/128) edge tiles
#define PAD_E   (NT * 128)       // 50048
#define ROWP    136              // padded row length (bf16 elems) -> 272B rows
#define PLANE_A 34816            // 128*ROWP*2 bytes, one 128-row bf16 plane
#define WELEMS  17408            // 128*ROWP elems per W plane

// ---------------- static device scratch (no allocation) ----------------
__device__ float g_c[2][N_EDGES * EMB];                  // cell state ping-pong
__device__ float g_H[4][N_EDGES * EMB];                  // per-gate GEMM outputs
__device__ __align__(16) __nv_bfloat16 g_hb[2][2][PAD_E * ROWP]; // h hi/lo planes, padded rows
__device__ __align__(16) __nv_bfloat16 g_W[5][2 * WELEMS];       // W[k][d] hi/lo, padded rows

__device__ __forceinline__ float sigf(float x) { return 1.0f / (1.0f + __expf(-x)); }

__device__ __forceinline__ uint32_t smem_u32(const void* p) {
    uint32_t a;
    asm("{ .reg .u64 t; cvta.to.shared.u64 t, %1; cvt.u32.u64 %0, t; }" : "=r"(a) : "l"(p));
    return a;
}
__device__ __forceinline__ void cpa16(uint32_t s, const void* g) {
    asm volatile("cp.async.cg.shared.global [%0], [%1], 16;" :: "r"(s), "l"(g) : "memory");
}
#define CP_COMMIT() asm volatile("cp.async.commit_group;" ::: "memory")
#define CP_WAIT0()  asm volatile("cp.async.wait_group 0;" ::: "memory")

__device__ __forceinline__ void ldsm_x4(uint32_t* r, uint32_t addr) {
    asm volatile("ldmatrix.sync.aligned.m8n8.x4.shared.b16 {%0,%1,%2,%3}, [%4];"
                 : "=r"(r[0]), "=r"(r[1]), "=r"(r[2]), "=r"(r[3]) : "r"(addr));
}
__device__ __forceinline__ void ldsm_x2t(uint32_t* r, uint32_t addr) {
    asm volatile("ldmatrix.sync.aligned.m8n8.x2.trans.shared.b16 {%0,%1}, [%2];"
                 : "=r"(r[0]), "=r"(r[1]) : "r"(addr));
}
__device__ __forceinline__ void mma16816(float* c, const uint32_t* a, const uint32_t* b) {
    asm volatile("mma.sync.aligned.m16n8k16.row.col.f32.bf16.bf16.f32 "
                 "{%0,%1,%2,%3}, {%4,%5,%6,%7}, {%8,%9}, {%0,%1,%2,%3};"
                 : "+f"(c[0]), "+f"(c[1]), "+f"(c[2]), "+f"(c[3])
                 : "r"(a[0]), "r"(a[1]), "r"(a[2]), "r"(a[3]), "r"(b[0]), "r"(b[1]));
}

// write one (e,d) h value as bf16 hi/lo into padded row-major planes
__device__ __forceinline__ void store_h_split(int buf, int e, int d, float h) {
    __nv_bfloat16 hi = __float2bfloat16(h);
    g_hb[buf][0][e * ROWP + d] = hi;
    g_hb[buf][1][e * ROWP + d] = __float2bfloat16(h - __bfloat162float(hi));
}

// ---------------------------------------------------------------------------
// Prep: W hi/lo planes, rows k = 0..127 (source rows roff+k), padded to ROWP
// ---------------------------------------------------------------------------
__global__ __launch_bounds__(256) void k_prep(
    const float* __restrict__ Wi, const float* __restrict__ Wo,
    const float* __restrict__ Wu, const float* __restrict__ Wf,
    const float* __restrict__ Wt)
{
    int g = blockIdx.x;
    const float* W;
    int roff;
    switch (g) {
        case 0: W = Wi; roff = HOFF; break;
        case 1: W = Wo; roff = HOFF; break;
        case 2: W = Wu; roff = HOFF; break;
        case 3: W = Wf; roff = HOFF; break;
        default: W = Wt; roff = VOCAB; break;
    }
    for (int idx = threadIdx.x; idx < 16384; idx += 256) {
        int k = idx >> 7;
        int d = idx & 127;
        float v = W[(roff + k) * EMB + d];
        __nv_bfloat16 hi = __float2bfloat16(v);
        g_W[g][k * ROWP + d] = hi;
        g_W[g][WELEMS + k * ROWP + d] = __float2bfloat16(v - __bfloat162float(hi));
    }
}

// ---------------------------------------------------------------------------
// Depth 0: one-hot gather + activations; writes c fp32 + h bf16-split
// ---------------------------------------------------------------------------
__global__ __launch_bounds__(256) void k_depth0(
    const int* __restrict__ node_ids, const int* __restrict__ edge_src,
    const int* __restrict__ edge_type,
    const float* __restrict__ Wi, const float* __restrict__ bi,
    const float* __restrict__ Wo, const float* __restrict__ bo,
    const float* __restrict__ Wu, const float* __restrict__ bu)
{
    int idx = blockIdx.x * blockDim.x + threadIdx.x;   // e*128 + d
    int e = idx >> 7, d = idx & 127;
    int nrow = node_ids[edge_src[e]];
    int brow = VOCAB + edge_type[e];
    float pi = Wi[nrow * EMB + d] + Wi[brow * EMB + d] + bi[d];
    float po = Wo[nrow * EMB + d] + Wo[brow * EMB + d] + bo[d];
    float pu = Wu[nrow * EMB + d] + Wu[brow * EMB + d] + bu[d];
    float i = sigf(pi), o = sigf(po), u = tanhf(pu);
    float c = i * u;
    float h = o * tanhf(c);
    if (e == 0) { h = 0.0f; c = 0.0f; }
    g_c[0][idx] = c;
    store_h_split(0, e, d, h);
}

// ---------------------------------------------------------------------------
// Tensor-core GEMM via mma.sync bf16-split:
//   g_H[gl] = h @ W[gbase+gl], gl in [0,ngates)
// Block = one 128-edge tile; A (h hi/lo) resident in smem; W double-buffered
// with cp.async across gates. Warp tile 64e x 32d, m16n8k16 frags.
// D += Ahi*Bhi + Alo*Bhi + Ahi*Blo.
// ---------------------------------------------------------------------------
#define MMA_SMEM (3 * 2 * PLANE_A)   // A(hi+lo) + 2 W buffers (hi+lo) = 208896 B

__global__ __launch_bounds__(256) void k_mma(int cur, int gbase, int ngates)
{
    extern __shared__ __align__(16) char sm[];
    const int tid  = threadIdx.x;
    const int lane = tid & 31;
    const int wid  = tid >> 5;
    const int wm   = wid >> 2;     // 0..1  -> edge offset wm*64
    const int wn   = wid & 3;      // 0..3  -> dim  offset wn*32
    const int tile = blockIdx.x;

    const uint32_t sA  = smem_u32(sm);
    const uint32_t sB0 = sA + 2 * PLANE_A;
    const uint32_t sB1 = sA + 4 * PLANE_A;

    // stage A hi/lo (two planes) + first W (hi+lo contiguous) via cp.async
    {
        const uint4* gAhi = (const uint4*)&g_hb[cur][0][(size_t)tile * 128 * ROWP];
        const uint4* gAlo = (const uint4*)&g_hb[cur][1][(size_t)tile * 128 * ROWP];
        const uint4* gW0  = (const uint4*)&g_W[gbase][0];
        for (int i = tid; i < 2176; i += 256) cpa16(sA + i * 16, gAhi + i);
        for (int i = tid; i < 2176; i += 256) cpa16(sA + PLANE_A + i * 16, gAlo + i);
        for (int i = tid; i < 4352; i += 256) cpa16(sB0 + i * 16, gW0 + i);
        CP_COMMIT();
        CP_WAIT0();
    }
    __syncthreads();

    // per-thread ldmatrix base addresses
    const uint32_t aBase = sA + (uint32_t)((wm * 64 + (lane & 15)) * ROWP + ((lane & 16) ? 8 : 0)) * 2;
    const uint32_t bRow  = (uint32_t)((lane & 15) * ROWP + wn * 32) * 2;

    for (int g = 0; g < ngates; g++) {
        // prefetch next gate's W into the other buffer
        if (g + 1 < ngates) {
            const uint4* gw = (const uint4*)&g_W[gbase + g + 1][0];
            uint32_t dst = ((g + 1) & 1) ? sB1 : sB0;
            for (int i = tid; i < 4352; i += 256) cpa16(dst + i * 16, gw + i);
            CP_COMMIT();
        }

        float acc[4][4][4];
        #pragma unroll
        for (int mf = 0; mf < 4; mf++)
            #pragma unroll
            for (int nf = 0; nf < 4; nf++)
                #pragma unroll
                for (int q = 0; q < 4; q++) acc[mf][nf][q] = 0.f;

        const uint32_t sB = ((g & 1) ? sB1 : sB0);

        #pragma unroll
        for (int term = 0; term < 3; term++) {
            const uint32_t aT = aBase + (term == 1 ? (uint32_t)PLANE_A : 0u);
            const uint32_t bT = sB + bRow + (term == 2 ? (uint32_t)PLANE_A : 0u);
            for (int ks = 0; ks < 8; ks++) {
                uint32_t aK = aT + ks * 32;           // +16 cols * 2B
                uint32_t bK = bT + ks * (16 * ROWP * 2); // +16 k-rows
                uint32_t afr[4][4];
                #pragma unroll
                for (int mf = 0; mf < 4; mf++)
                    ldsm_x4(afr[mf], aK + mf * (16 * ROWP * 2));
                uint32_t bfr[4][2];
                #pragma unroll
                for (int nf = 0; nf < 4; nf++)
                    ldsm_x2t(bfr[nf], bK + nf * 16);
                #pragma unroll
                for (int mf = 0; mf < 4; mf++)
                    #pragma unroll
                    for (int nf = 0; nf < 4; nf++)
                        mma16816(acc[mf][nf], afr[mf], bfr[nf]);
            }
        }

        // epilogue: write this gate's H tile
        float* __restrict__ H = g_H[g];   // (final pass: gbase=4, g=0 -> g_H[0])
        #pragma unroll
        for (int mf = 0; mf < 4; mf++) {
            int e0 = tile * 128 + wm * 64 + mf * 16 + (lane >> 2);
            #pragma unroll
            for (int nf = 0; nf < 4; nf++) {
                int d0 = wn * 32 + nf * 8 + (lane & 3) * 2;
                if (e0 < N_EDGES)
                    *(float2*)&H[e0 * EMB + d0] = make_float2(acc[mf][nf][0], acc[mf][nf][1]);
                if (e0 + 8 < N_EDGES)
                    *(float2*)&H[(e0 + 8) * EMB + d0] = make_float2(acc[mf][nf][2], acc[mf][nf][3]);
            }
        }

        if (g + 1 < ngates) {
            CP_WAIT0();
            __syncthreads();   // next buffer ready; all warps done reading current
        }
    }
}

// ---------------------------------------------------------------------------
// Update: gather per-gate GEMM rows over 6 neighbors + one-hot rows + biases,
// LSTM math, write c fp32 + h bf16-split. 2 edges per 256-thread block.
// ---------------------------------------------------------------------------
__global__ __launch_bounds__(256) void k_update(
    int cur, int nxt,
    const int* __restrict__ node_ids, const int* __restrict__ edge_src,
    const int* __restrict__ edge_type, const int* __restrict__ bond_list,
    const float* __restrict__ Wi, const float* __restrict__ bi,
    const float* __restrict__ Wo, const float* __restrict__ bo,
    const float* __restrict__ Wf, const float* __restrict__ bf,
    const float* __restrict__ Wu, const float* __restrict__ bu)
{
    __shared__ int s_b[2 * MAX_NB];
    __shared__ int s_nr[2], s_br[2];

    const float* __restrict__ Hi = g_H[0];
    const float* __restrict__ Ho = g_H[1];
    const float* __restrict__ Hu = g_H[2];
    const float* __restrict__ Hf = g_H[3];
    const float* __restrict__ c_old = g_c[cur];
    float* __restrict__ c_new = g_c[nxt];

    const int tid = threadIdx.x;
    const int e0  = blockIdx.x * 2;

    if (tid < 2 * MAX_NB) {
        s_b[tid] = bond_list[e0 * MAX_NB + tid];
    } else if (tid < 2 * MAX_NB + 2) {
        int e = tid - 2 * MAX_NB;
        s_nr[e] = node_ids[edge_src[e0 + e]];
    } else if (tid < 2 * MAX_NB + 4) {
        int e = tid - 2 * MAX_NB - 2;
        s_br[e] = VOCAB + edge_type[e0 + e];
    }
    __syncthreads();

    const int le = tid >> 7;
    const int d  = tid & 127;
    const int e  = e0 + le;

    int b[MAX_NB];
    #pragma unroll
    for (int k = 0; k < MAX_NB; k++) b[k] = s_b[le * MAX_NB + k] * EMB + d;

    float vi[MAX_NB], vo[MAX_NB], vu[MAX_NB], vf[MAX_NB], vc[MAX_NB];
    #pragma unroll
    for (int k = 0; k < MAX_NB; k++) {
        vi[k] = Hi[b[k]];
        vo[k] = Ho[b[k]];
        vu[k] = Hu[b[k]];
        vf[k] = Hf[b[k]];
        vc[k] = c_old[b[k]];
    }

    float si = 0.f, so = 0.f, su = 0.f;
    #pragma unroll
    for (int k = 0; k < MAX_NB; k++) { si += vi[k]; so += vo[k]; su += vu[k]; }

    const int nr = s_nr[le], br = s_br[le];
    float i_g = sigf(si + Wi[nr * EMB + d] + Wi[br * EMB + d] + bi[d]);
    float o_g = sigf(so + Wo[nr * EMB + d] + Wo[br * EMB + d] + bo[d]);
    float u_g = tanhf(su + Wu[nr * EMB + d] + Wu[br * EMB + d] + bu[d]);
    float pre_f = Wf[nr * EMB + d] + Wf[br * EMB + d] + bf[d];

    float c_acc = i_g * u_g;
    #pragma unroll
    for (int k = 0; k < MAX_NB; k++)
        c_acc += sigf(vf[k] + pre_f) * vc[k];

    float h = o_g * tanhf(c_acc);
    if (e == 0) { h = 0.f; c_acc = 0.f; }
    c_new[e * EMB + d] = c_acc;
    store_h_split(nxt, e, d, h);
}

// ---------------------------------------------------------------------------
// Final node projection: out = relu(Wt[nid] + bt + sum_k Ht[adj[n,k]])
// ---------------------------------------------------------------------------
__global__ __launch_bounds__(256) void k_final(
    const int* __restrict__ node_ids, const int* __restrict__ adj_list,
    const float* __restrict__ Wt, const float* __restrict__ bt,
    float* __restrict__ out)
{
    __shared__ int s_a[2 * MAX_NB];
    __shared__ int s_nid[2];

    const float* __restrict__ Ht = g_H[0];

    const int tid = threadIdx.x;
    const int n0  = blockIdx.x * 2;

    if (tid < 2 * MAX_NB) {
        s_a[tid] = adj_list[n0 * MAX_NB + tid];
    } else if (tid < 2 * MAX_NB + 2) {
        int n = tid - 2 * MAX_NB;
        s_nid[n] = node_ids[n0 + n];
    }
    __syncthreads();

    const int ln = tid >> 7;
    const int d  = tid & 127;
    const int n  = n0 + ln;

    float s = 0.f;
    #pragma unroll
    for (int k = 0; k < MAX_NB; k++)
        s += Ht[s_a[ln * MAX_NB + k] * EMB + d];

    float v = s + Wt[s_nid[ln] * EMB + d] + bt[d];
    v = fmaxf(v, 0.f);
    if (n == 0) v = 0.f;
    out[n * EMB + d] = v;
}

// ---------------------------------------------------------------------------
extern "C" void kernel_launch(void* const* d_in, const int* in_sizes, int n_in,
                              void* d_out, int out_size)
{
    const int*   node_ids  = (const int*)d_in[0];
    const int*   edge_src  = (const int*)d_in[1];
    const int*   edge_type = (const int*)d_in[2];
    const int*   adj_list  = (const int*)d_in[3];
    const int*   bond_list = (const int*)d_in[4];
    const float* Wi = (const float*)d_in[5];
    const float* bi = (const float*)d_in[6];
    const float* Wo = (const float*)d_in[7];
    const float* bo = (const float*)d_in[8];
    const float* Wf = (const float*)d_in[9];
    const float* bf = (const float*)d_in[10];
    const float* Wu = (const float*)d_in[11];
    const float* bu = (const float*)d_in[12];
    const float* Wt = (const float*)d_in[13];
    const float* bt = (const float*)d_in[14];
    float* out = (float*)d_out;

    cudaFuncSetAttribute(k_mma, cudaFuncAttributeMaxDynamicSharedMemorySize, MMA_SMEM);

    k_prep<<<5, 256>>>(Wi, Wo, Wu, Wf, Wt);
    k_depth0<<<(N_EDGES * EMB) / 256, 256>>>(node_ids, edge_src, edge_type,
                                             Wi, bi, Wo, bo, Wu, bu);

    int cur = 0, nxt = 1;
    for (int depth = 1; depth < 4; depth++) {
        k_mma<<<NT, 256, MMA_SMEM>>>(cur, 0, 4);
        k_update<<<N_EDGES / 2, 256>>>(cur, nxt, node_ids, edge_src, edge_type,
                                       bond_list, Wi, bi, Wo, bo, Wf, bf, Wu, bu);
        int t = cur; cur = nxt; nxt = t;
    }

    k_mma<<<NT, 256, MMA_SMEM>>>(cur, 4, 1);   // Ht -> g_H[0]
    k_final<<<N_NODES / 2, 256>>>(node_ids, adj_list, Wt, bt, out);
}

// round 7
// speedup vs baseline: 2.8251x; 1.0312x over previous
#include <cuda_runtime.h>
#include <cuda_bf16.h>
#include <cuda_fp16.h>
#include <math.h>
#include <stdint.h>

#define VOCAB   100
#define NBOND   4
#define EMB     128
#define N_NODES 25000
#define N_EDGES 50000
#define MAX_NB  6
#define HOFF    104
#define NT      391              // ceil(50000/128) edge tiles
#define PAD_E   (NT * 128)       // 50048
#define ROWP    136              // padded row length (bf16 elems) -> 272B rows
#define PLANE_A 34816            // 128*ROWP*2 bytes, one 128-row bf16 plane
#define WELEMS  17408            // 128*ROWP elems per W plane

// ---------------- static device scratch (no allocation) ----------------
__device__ float g_c[2][N_EDGES * EMB];                  // cell state ping-pong
__device__ uint32_t g_P01[N_EDGES * EMB];                // half2(Hi,Ho) per (e,d)
__device__ uint32_t g_P23[N_EDGES * EMB];                // half2(Hu,Hf) per (e,d)
__device__ float g_Ht[N_EDGES * EMB];                    // final-pass fp32 Ht
__device__ __align__(16) __nv_bfloat16 g_hb[2][2][PAD_E * ROWP]; // h hi/lo planes, padded rows
__device__ __align__(16) __nv_bfloat16 g_W[5][2 * WELEMS];       // W[k][d] hi/lo, padded rows

__device__ __forceinline__ float sigf(float x) { return 1.0f / (1.0f + __expf(-x)); }

__device__ __forceinline__ uint32_t smem_u32(const void* p) {
    uint32_t a;
    asm("{ .reg .u64 t; cvta.to.shared.u64 t, %1; cvt.u32.u64 %0, t; }" : "=r"(a) : "l"(p));
    return a;
}
__device__ __forceinline__ void cpa16(uint32_t s, const void* g) {
    asm volatile("cp.async.cg.shared.global [%0], [%1], 16;" :: "r"(s), "l"(g) : "memory");
}
#define CP_COMMIT() asm volatile("cp.async.commit_group;" ::: "memory")
#define CP_WAIT0()  asm volatile("cp.async.wait_group 0;" ::: "memory")

__device__ __forceinline__ void ldsm_x4(uint32_t* r, uint32_t addr) {
    asm volatile("ldmatrix.sync.aligned.m8n8.x4.shared.b16 {%0,%1,%2,%3}, [%4];"
                 : "=r"(r[0]), "=r"(r[1]), "=r"(r[2]), "=r"(r[3]) : "r"(addr));
}
__device__ __forceinline__ void ldsm_x2t(uint32_t* r, uint32_t addr) {
    asm volatile("ldmatrix.sync.aligned.m8n8.x2.trans.shared.b16 {%0,%1}, [%2];"
                 : "=r"(r[0]), "=r"(r[1]) : "r"(addr));
}
__device__ __forceinline__ void mma16816(float* c, const uint32_t* a, const uint32_t* b) {
    asm volatile("mma.sync.aligned.m16n8k16.row.col.f32.bf16.bf16.f32 "
                 "{%0,%1,%2,%3}, {%4,%5,%6,%7}, {%8,%9}, {%0,%1,%2,%3};"
                 : "+f"(c[0]), "+f"(c[1]), "+f"(c[2]), "+f"(c[3])
                 : "r"(a[0]), "r"(a[1]), "r"(a[2]), "r"(a[3]), "r"(b[0]), "r"(b[1]));
}

// write one (e,d) h value as bf16 hi/lo into padded row-major planes
__device__ __forceinline__ void store_h_split(int buf, int e, int d, float h) {
    __nv_bfloat16 hi = __float2bfloat16(h);
    g_hb[buf][0][e * ROWP + d] = hi;
    g_hb[buf][1][e * ROWP + d] = __float2bfloat16(h - __bfloat162float(hi));
}

// ---------------------------------------------------------------------------
// Prep: W hi/lo planes, rows k = 0..127 (source rows roff+k), padded to ROWP
// ---------------------------------------------------------------------------
__global__ __launch_bounds__(256) void k_prep(
    const float* __restrict__ Wi, const float* __restrict__ Wo,
    const float* __restrict__ Wu, const float* __restrict__ Wf,
    const float* __restrict__ Wt)
{
    int g = blockIdx.x;
    const float* W;
    int roff;
    switch (g) {
        case 0: W = Wi; roff = HOFF; break;
        case 1: W = Wo; roff = HOFF; break;
        case 2: W = Wu; roff = HOFF; break;
        case 3: W = Wf; roff = HOFF; break;
        default: W = Wt; roff = VOCAB; break;
    }
    for (int idx = threadIdx.x; idx < 16384; idx += 256) {
        int k = idx >> 7;
        int d = idx & 127;
        float v = W[(roff + k) * EMB + d];
        __nv_bfloat16 hi = __float2bfloat16(v);
        g_W[g][k * ROWP + d] = hi;
        g_W[g][WELEMS + k * ROWP + d] = __float2bfloat16(v - __bfloat162float(hi));
    }
}

// ---------------------------------------------------------------------------
// Depth 0: one-hot gather + activations; writes c fp32 + h bf16-split
// ---------------------------------------------------------------------------
__global__ __launch_bounds__(256) void k_depth0(
    const int* __restrict__ node_ids, const int* __restrict__ edge_src,
    const int* __restrict__ edge_type,
    const float* __restrict__ Wi, const float* __restrict__ bi,
    const float* __restrict__ Wo, const float* __restrict__ bo,
    const float* __restrict__ Wu, const float* __restrict__ bu)
{
    int idx = blockIdx.x * blockDim.x + threadIdx.x;   // e*128 + d
    int e = idx >> 7, d = idx & 127;
    int nrow = node_ids[edge_src[e]];
    int brow = VOCAB + edge_type[e];
    float pi = Wi[nrow * EMB + d] + Wi[brow * EMB + d] + bi[d];
    float po = Wo[nrow * EMB + d] + Wo[brow * EMB + d] + bo[d];
    float pu = Wu[nrow * EMB + d] + Wu[brow * EMB + d] + bu[d];
    float i = sigf(pi), o = sigf(po), u = tanhf(pu);
    float c = i * u;
    float h = o * tanhf(c);
    if (e == 0) { h = 0.0f; c = 0.0f; }
    g_c[0][idx] = c;
    store_h_split(0, e, d, h);
}

// ---------------------------------------------------------------------------
// Tensor-core GEMM via mma.sync bf16-split:
//   gate preacts for gate gbase+g -> fp16 packed planes (or fp32 g_Ht if final)
// Block = one 128-edge tile; A (h hi/lo) resident in smem; W double-buffered
// with cp.async across gates. Warp tile 64e x 32d, m16n8k16 frags.
// D += Ahi*Bhi + Alo*Bhi + Ahi*Blo.
// ---------------------------------------------------------------------------
#define MMA_SMEM (3 * 2 * PLANE_A)   // A(hi+lo) + 2 W buffers (hi+lo) = 208896 B

__global__ __launch_bounds__(256) void k_mma(int cur, int gbase, int ngates)
{
    extern __shared__ __align__(16) char sm[];
    const int tid  = threadIdx.x;
    const int lane = tid & 31;
    const int wid  = tid >> 5;
    const int wm   = wid >> 2;     // 0..1  -> edge offset wm*64
    const int wn   = wid & 3;      // 0..3  -> dim  offset wn*32
    const int tile = blockIdx.x;

    const uint32_t sA  = smem_u32(sm);
    const uint32_t sB0 = sA + 2 * PLANE_A;
    const uint32_t sB1 = sA + 4 * PLANE_A;

    // stage A hi/lo (two planes) + first W (hi+lo contiguous) via cp.async
    {
        const uint4* gAhi = (const uint4*)&g_hb[cur][0][(size_t)tile * 128 * ROWP];
        const uint4* gAlo = (const uint4*)&g_hb[cur][1][(size_t)tile * 128 * ROWP];
        const uint4* gW0  = (const uint4*)&g_W[gbase][0];
        for (int i = tid; i < 2176; i += 256) cpa16(sA + i * 16, gAhi + i);
        for (int i = tid; i < 2176; i += 256) cpa16(sA + PLANE_A + i * 16, gAlo + i);
        for (int i = tid; i < 4352; i += 256) cpa16(sB0 + i * 16, gW0 + i);
        CP_COMMIT();
        CP_WAIT0();
    }
    __syncthreads();

    // per-thread ldmatrix base addresses
    const uint32_t aBase = sA + (uint32_t)((wm * 64 + (lane & 15)) * ROWP + ((lane & 16) ? 8 : 0)) * 2;
    const uint32_t bRow  = (uint32_t)((lane & 15) * ROWP + wn * 32) * 2;

    for (int g = 0; g < ngates; g++) {
        // prefetch next gate's W into the other buffer
        if (g + 1 < ngates) {
            const uint4* gw = (const uint4*)&g_W[gbase + g + 1][0];
            uint32_t dst = ((g + 1) & 1) ? sB1 : sB0;
            for (int i = tid; i < 4352; i += 256) cpa16(dst + i * 16, gw + i);
            CP_COMMIT();
        }

        float acc[4][4][4];
        #pragma unroll
        for (int mf = 0; mf < 4; mf++)
            #pragma unroll
            for (int nf = 0; nf < 4; nf++)
                #pragma unroll
                for (int q = 0; q < 4; q++) acc[mf][nf][q] = 0.f;

        const uint32_t sB = ((g & 1) ? sB1 : sB0);

        #pragma unroll
        for (int term = 0; term < 3; term++) {
            const uint32_t aT = aBase + (term == 1 ? (uint32_t)PLANE_A : 0u);
            const uint32_t bT = sB + bRow + (term == 2 ? (uint32_t)PLANE_A : 0u);
            for (int ks = 0; ks < 8; ks++) {
                uint32_t aK = aT + ks * 32;              // +16 cols * 2B
                uint32_t bK = bT + ks * (16 * ROWP * 2); // +16 k-rows
                uint32_t afr[4][4];
                #pragma unroll
                for (int mf = 0; mf < 4; mf++)
                    ldsm_x4(afr[mf], aK + mf * (16 * ROWP * 2));
                uint32_t bfr[4][2];
                #pragma unroll
                for (int nf = 0; nf < 4; nf++)
                    ldsm_x2t(bfr[nf], bK + nf * 16);
                #pragma unroll
                for (int mf = 0; mf < 4; mf++)
                    #pragma unroll
                    for (int nf = 0; nf < 4; nf++)
                        mma16816(acc[mf][nf], afr[mf], bfr[nf]);
            }
        }

        // epilogue
        if (gbase == 4) {
            // final pass: fp32 Ht
            float* __restrict__ H = g_Ht;
            #pragma unroll
            for (int mf = 0; mf < 4; mf++) {
                int e0 = tile * 128 + wm * 64 + mf * 16 + (lane >> 2);
                #pragma unroll
                for (int nf = 0; nf < 4; nf++) {
                    int d0 = wn * 32 + nf * 8 + (lane & 3) * 2;
                    if (e0 < N_EDGES)
                        *(float2*)&H[e0 * EMB + d0] = make_float2(acc[mf][nf][0], acc[mf][nf][1]);
                    if (e0 + 8 < N_EDGES)
                        *(float2*)&H[(e0 + 8) * EMB + d0] = make_float2(acc[mf][nf][2], acc[mf][nf][3]);
                }
            }
        } else {
            // gate pass: fp16 component (g&1) of packed plane (g>>1)
            __half* __restrict__ Hh = (g & 2) ? (__half*)g_P23 : (__half*)g_P01;
            const int comp = g & 1;
            #pragma unroll
            for (int mf = 0; mf < 4; mf++) {
                int e0 = tile * 128 + wm * 64 + mf * 16 + (lane >> 2);
                #pragma unroll
                for (int nf = 0; nf < 4; nf++) {
                    int d0 = wn * 32 + nf * 8 + (lane & 3) * 2;
                    if (e0 < N_EDGES) {
                        Hh[2 * (e0 * EMB + d0)     + comp] = __float2half_rn(acc[mf][nf][0]);
                        Hh[2 * (e0 * EMB + d0 + 1) + comp] = __float2half_rn(acc[mf][nf][1]);
                    }
                    if (e0 + 8 < N_EDGES) {
                        Hh[2 * ((e0 + 8) * EMB + d0)     + comp] = __float2half_rn(acc[mf][nf][2]);
                        Hh[2 * ((e0 + 8) * EMB + d0 + 1) + comp] = __float2half_rn(acc[mf][nf][3]);
                    }
                }
            }
        }

        if (g + 1 < ngates) {
            CP_WAIT0();
            __syncthreads();   // next buffer ready; all warps done reading current
        }
    }
}

// ---------------------------------------------------------------------------
// Update: gather packed fp16 gate preacts over 6 neighbors + one-hot rows,
// LSTM math, write c fp32 + h bf16-split. 2 edges per 256-thread block.
// ---------------------------------------------------------------------------
__global__ __launch_bounds__(256) void k_update(
    int cur, int nxt,
    const int* __restrict__ node_ids, const int* __restrict__ edge_src,
    const int* __restrict__ edge_type, const int* __restrict__ bond_list,
    const float* __restrict__ Wi, const float* __restrict__ bi,
    const float* __restrict__ Wo, const float* __restrict__ bo,
    const float* __restrict__ Wf, const float* __restrict__ bf,
    const float* __restrict__ Wu, const float* __restrict__ bu)
{
    __shared__ int s_b[2 * MAX_NB];
    __shared__ int s_nr[2], s_br[2];

    const uint32_t* __restrict__ P01 = g_P01;
    const uint32_t* __restrict__ P23 = g_P23;
    const float* __restrict__ c_old = g_c[cur];
    float* __restrict__ c_new = g_c[nxt];

    const int tid = threadIdx.x;
    const int e0  = blockIdx.x * 2;

    if (tid < 2 * MAX_NB) {
        s_b[tid] = bond_list[e0 * MAX_NB + tid];
    } else if (tid < 2 * MAX_NB + 2) {
        int e = tid - 2 * MAX_NB;
        s_nr[e] = node_ids[edge_src[e0 + e]];
    } else if (tid < 2 * MAX_NB + 4) {
        int e = tid - 2 * MAX_NB - 2;
        s_br[e] = VOCAB + edge_type[e0 + e];
    }
    __syncthreads();

    const int le = tid >> 7;
    const int d  = tid & 127;
    const int e  = e0 + le;

    int b[MAX_NB];
    #pragma unroll
    for (int k = 0; k < MAX_NB; k++) b[k] = s_b[le * MAX_NB + k] * EMB + d;

    // batched independent gathers (high MLP): 18 loads
    uint32_t w01[MAX_NB], w23[MAX_NB];
    float vc[MAX_NB];
    #pragma unroll
    for (int k = 0; k < MAX_NB; k++) {
        w01[k] = P01[b[k]];
        w23[k] = P23[b[k]];
        vc[k]  = c_old[b[k]];
    }

    float si = 0.f, so = 0.f, su = 0.f;
    float vf[MAX_NB];
    #pragma unroll
    for (int k = 0; k < MAX_NB; k++) {
        float2 g01 = __half22float2(*(__half2*)&w01[k]);
        float2 g23 = __half22float2(*(__half2*)&w23[k]);
        si += g01.x;
        so += g01.y;
        su += g23.x;
        vf[k] = g23.y;
    }

    const int nr = s_nr[le], br = s_br[le];
    float i_g = sigf(si + Wi[nr * EMB + d] + Wi[br * EMB + d] + bi[d]);
    float o_g = sigf(so + Wo[nr * EMB + d] + Wo[br * EMB + d] + bo[d]);
    float u_g = tanhf(su + Wu[nr * EMB + d] + Wu[br * EMB + d] + bu[d]);
    float pre_f = Wf[nr * EMB + d] + Wf[br * EMB + d] + bf[d];

    float c_acc = i_g * u_g;
    #pragma unroll
    for (int k = 0; k < MAX_NB; k++)
        c_acc += sigf(vf[k] + pre_f) * vc[k];

    float h = o_g * tanhf(c_acc);
    if (e == 0) { h = 0.f; c_acc = 0.f; }
    c_new[e * EMB + d] = c_acc;
    store_h_split(nxt, e, d, h);
}

// ---------------------------------------------------------------------------
// Final node projection: out = relu(Wt[nid] + bt + sum_k Ht[adj[n,k]])
// ---------------------------------------------------------------------------
__global__ __launch_bounds__(256) void k_final(
    const int* __restrict__ node_ids, const int* __restrict__ adj_list,
    const float* __restrict__ Wt, const float* __restrict__ bt,
    float* __restrict__ out)
{
    __shared__ int s_a[2 * MAX_NB];
    __shared__ int s_nid[2];

    const float* __restrict__ Ht = g_Ht;

    const int tid = threadIdx.x;
    const int n0  = blockIdx.x * 2;

    if (tid < 2 * MAX_NB) {
        s_a[tid] = adj_list[n0 * MAX_NB + tid];
    } else if (tid < 2 * MAX_NB + 2) {
        int n = tid - 2 * MAX_NB;
        s_nid[n] = node_ids[n0 + n];
    }
    __syncthreads();

    const int ln = tid >> 7;
    const int d  = tid & 127;
    const int n  = n0 + ln;

    float s = 0.f;
    #pragma unroll
    for (int k = 0; k < MAX_NB; k++)
        s += Ht[s_a[ln * MAX_NB + k] * EMB + d];

    float v = s + Wt[s_nid[ln] * EMB + d] + bt[d];
    v = fmaxf(v, 0.f);
    if (n == 0) v = 0.f;
    out[n * EMB + d] = v;
}

// ---------------------------------------------------------------------------
extern "C" void kernel_launch(void* const* d_in, const int* in_sizes, int n_in,
                              void* d_out, int out_size)
{
    const int*   node_ids  = (const int*)d_in[0];
    const int*   edge_src  = (const int*)d_in[1];
    const int*   edge_type = (const int*)d_in[2];
    const int*   adj_list  = (const int*)d_in[3];
    const int*   bond_list = (const int*)d_in[4];
    const float* Wi = (const float*)d_in[5];
    const float* bi = (const float*)d_in[6];
    const float* Wo = (const float*)d_in[7];
    const float* bo = (const float*)d_in[8];
    const float* Wf = (const float*)d_in[9];
    const float* bf = (const float*)d_in[10];
    const float* Wu = (const float*)d_in[11];
    const float* bu = (const float*)d_in[12];
    const float* Wt = (const float*)d_in[13];
    const float* bt = (const float*)d_in[14];
    float* out = (float*)d_out;

    cudaFuncSetAttribute(k_mma, cudaFuncAttributeMaxDynamicSharedMemorySize, MMA_SMEM);

    k_prep<<<5, 256>>>(Wi, Wo, Wu, Wf, Wt);
    k_depth0<<<(N_EDGES * EMB) / 256, 256>>>(node_ids, edge_src, edge_type,
                                             Wi, bi, Wo, bo, Wu, bu);

    int cur = 0, nxt = 1;
    for (int depth = 1; depth < 4; depth++) {
        k_mma<<<NT, 256, MMA_SMEM>>>(cur, 0, 4);
        k_update<<<N_EDGES / 2, 256>>>(cur, nxt, node_ids, edge_src, edge_type,
                                       bond_list, Wi, bi, Wo, bo, Wf, bf, Wu, bu);
        int t = cur; cur = nxt; nxt = t;
    }

    k_mma<<<NT, 256, MMA_SMEM>>>(cur, 4, 1);   // Ht -> g_Ht (fp32)
    k_final<<<N_NODES / 2, 256>>>(node_ids, adj_list, Wt, bt, out);
}

// round 8
// speedup vs baseline: 3.5192x; 1.2457x over previous
#include <cuda_runtime.h>
#include <cuda_bf16.h>
#include <cuda_fp16.h>
#include <math.h>
#include <stdint.h>

#define VOCAB   100
#define NBOND   4
#define EMB     128
#define N_NODES 25000
#define N_EDGES 50000
#define MAX_NB  6
#define HOFF    104
#define NT      391              // ceil(50000/128) edge tiles
#define PAD_E   (NT * 128)       // 50048
#define ROWP    136              // padded row length (bf16 elems) -> 272B rows
#define PLANE_A 34816            // 128*ROWP*2 bytes, one 128-row bf16 plane
#define WELEMS  17408            // 128*ROWP elems per W plane

// ---------------- static device scratch (no allocation) ----------------
__device__ float g_c[2][N_EDGES * EMB];                  // cell state ping-pong
__device__ uint32_t g_P01[N_EDGES * EMB];                // half2(Hi,Ho) per (e,d)
__device__ uint32_t g_P23[N_EDGES * EMB];                // half2(Hu,Hf) per (e,d)
__device__ float g_Ht[N_EDGES * EMB];                    // final-pass fp32 Ht
__device__ __align__(16) __nv_bfloat16 g_hb[2][2][PAD_E * ROWP]; // h hi/lo planes, padded rows
__device__ __align__(16) __nv_bfloat16 g_W[5][2 * WELEMS];       // W[k][d] hi/lo, padded rows

// fast activations: tanh.approx.f32 (sm_75+ baseline PTX)
__device__ __forceinline__ float tanhfast(float x) {
    float y;
    asm("tanh.approx.f32 %0, %1;" : "=f"(y) : "f"(x));
    return y;
}
__device__ __forceinline__ float sigfast(float x) {
    return fmaf(0.5f, tanhfast(0.5f * x), 0.5f);
}

__device__ __forceinline__ uint32_t smem_u32(const void* p) {
    uint32_t a;
    asm("{ .reg .u64 t; cvta.to.shared.u64 t, %1; cvt.u32.u64 %0, t; }" : "=r"(a) : "l"(p));
    return a;
}
__device__ __forceinline__ void cpa16(uint32_t s, const void* g) {
    asm volatile("cp.async.cg.shared.global [%0], [%1], 16;" :: "r"(s), "l"(g) : "memory");
}
#define CP_COMMIT() asm volatile("cp.async.commit_group;" ::: "memory")
#define CP_WAIT0()  asm volatile("cp.async.wait_group 0;" ::: "memory")

__device__ __forceinline__ void ldsm_x4(uint32_t* r, uint32_t addr) {
    asm volatile("ldmatrix.sync.aligned.m8n8.x4.shared.b16 {%0,%1,%2,%3}, [%4];"
                 : "=r"(r[0]), "=r"(r[1]), "=r"(r[2]), "=r"(r[3]) : "r"(addr));
}
__device__ __forceinline__ void ldsm_x2t(uint32_t* r, uint32_t addr) {
    asm volatile("ldmatrix.sync.aligned.m8n8.x2.trans.shared.b16 {%0,%1}, [%2];"
                 : "=r"(r[0]), "=r"(r[1]) : "r"(addr));
}
__device__ __forceinline__ void mma16816(float* c, const uint32_t* a, const uint32_t* b) {
    asm volatile("mma.sync.aligned.m16n8k16.row.col.f32.bf16.bf16.f32 "
                 "{%0,%1,%2,%3}, {%4,%5,%6,%7}, {%8,%9}, {%0,%1,%2,%3};"
                 : "+f"(c[0]), "+f"(c[1]), "+f"(c[2]), "+f"(c[3])
                 : "r"(a[0]), "r"(a[1]), "r"(a[2]), "r"(a[3]), "r"(b[0]), "r"(b[1]));
}
__device__ __forceinline__ uint32_t prmt(uint32_t a, uint32_t b, uint32_t s) {
    uint32_t d;
    asm("prmt.b32 %0, %1, %2, %3;" : "=r"(d) : "r"(a), "r"(b), "r"(s));
    return d;
}
__device__ __forceinline__ uint32_t f2h2(float a, float b) {
    __half2 h = __floats2half2_rn(a, b);   // low = a
    return *(uint32_t*)&h;
}

// write one (e,d) h value as bf16 hi/lo into padded row-major planes
__device__ __forceinline__ void store_h_split(int buf, int e, int d, float h) {
    __nv_bfloat16 hi = __float2bfloat16(h);
    g_hb[buf][0][e * ROWP + d] = hi;
    g_hb[buf][1][e * ROWP + d] = __float2bfloat16(h - __bfloat162float(hi));
}

// ---------------------------------------------------------------------------
// Prep: W hi/lo planes, rows k = 0..127 (source rows roff+k), padded to ROWP
// ---------------------------------------------------------------------------
__global__ __launch_bounds__(256) void k_prep(
    const float* __restrict__ Wi, const float* __restrict__ Wo,
    const float* __restrict__ Wu, const float* __restrict__ Wf,
    const float* __restrict__ Wt)
{
    int g = blockIdx.x;
    const float* W;
    int roff;
    switch (g) {
        case 0: W = Wi; roff = HOFF; break;
        case 1: W = Wo; roff = HOFF; break;
        case 2: W = Wu; roff = HOFF; break;
        case 3: W = Wf; roff = HOFF; break;
        default: W = Wt; roff = VOCAB; break;
    }
    for (int idx = threadIdx.x; idx < 16384; idx += 256) {
        int k = idx >> 7;
        int d = idx & 127;
        float v = W[(roff + k) * EMB + d];
        __nv_bfloat16 hi = __float2bfloat16(v);
        g_W[g][k * ROWP + d] = hi;
        g_W[g][WELEMS + k * ROWP + d] = __float2bfloat16(v - __bfloat162float(hi));
    }
}

// ---------------------------------------------------------------------------
// Depth 0: one-hot gather + activations; writes c fp32 + h bf16-split
// ---------------------------------------------------------------------------
__global__ __launch_bounds__(256) void k_depth0(
    const int* __restrict__ node_ids, const int* __restrict__ edge_src,
    const int* __restrict__ edge_type,
    const float* __restrict__ Wi, const float* __restrict__ bi,
    const float* __restrict__ Wo, const float* __restrict__ bo,
    const float* __restrict__ Wu, const float* __restrict__ bu)
{
    int idx = blockIdx.x * blockDim.x + threadIdx.x;   // e*128 + d
    int e = idx >> 7, d = idx & 127;
    int nrow = node_ids[edge_src[e]];
    int brow = VOCAB + edge_type[e];
    float pi = Wi[nrow * EMB + d] + Wi[brow * EMB + d] + bi[d];
    float po = Wo[nrow * EMB + d] + Wo[brow * EMB + d] + bo[d];
    float pu = Wu[nrow * EMB + d] + Wu[brow * EMB + d] + bu[d];
    float i = sigfast(pi), o = sigfast(po), u = tanhfast(pu);
    float c = i * u;
    float h = o * tanhfast(c);
    if (e == 0) { h = 0.0f; c = 0.0f; }
    g_c[0][idx] = c;
    store_h_split(0, e, d, h);
}

// ---------------------------------------------------------------------------
// Tensor-core GEMM via mma.sync bf16-split. Gate passes (gbase=0, ngates=4):
// gates processed in pairs; even gate's result retained as packed halves,
// merged with the odd gate via prmt, stored as coalesced uint2 words into
// g_P01 / g_P23. Final pass (gbase=4, ngates=1): fp32 into g_Ht.
// ---------------------------------------------------------------------------
#define MMA_SMEM (3 * 2 * PLANE_A)   // A(hi+lo) + 2 W buffers (hi+lo) = 208896 B

__global__ __launch_bounds__(256) void k_mma(int cur, int gbase, int ngates)
{
    extern __shared__ __align__(16) char sm[];
    const int tid  = threadIdx.x;
    const int lane = tid & 31;
    const int wid  = tid >> 5;
    const int wm   = wid >> 2;     // 0..1  -> edge offset wm*64
    const int wn   = wid & 3;      // 0..3  -> dim  offset wn*32
    const int tile = blockIdx.x;

    const uint32_t sA  = smem_u32(sm);
    const uint32_t sB0 = sA + 2 * PLANE_A;
    const uint32_t sB1 = sA + 4 * PLANE_A;

    // stage A hi/lo (two planes) + first W (hi+lo contiguous) via cp.async
    {
        const uint4* gAhi = (const uint4*)&g_hb[cur][0][(size_t)tile * 128 * ROWP];
        const uint4* gAlo = (const uint4*)&g_hb[cur][1][(size_t)tile * 128 * ROWP];
        const uint4* gW0  = (const uint4*)&g_W[gbase][0];
        for (int i = tid; i < 2176; i += 256) cpa16(sA + i * 16, gAhi + i);
        for (int i = tid; i < 2176; i += 256) cpa16(sA + PLANE_A + i * 16, gAlo + i);
        for (int i = tid; i < 4352; i += 256) cpa16(sB0 + i * 16, gW0 + i);
        CP_COMMIT();
        CP_WAIT0();
    }
    __syncthreads();

    // per-thread ldmatrix base addresses
    const uint32_t aBase = sA + (uint32_t)((wm * 64 + (lane & 15)) * ROWP + ((lane & 16) ? 8 : 0)) * 2;
    const uint32_t bRow  = (uint32_t)((lane & 15) * ROWP + wn * 32) * 2;

    uint32_t hold[32];   // even gate's halves: per (mf,nf): [d0,d0+1]@e0, [d0,d0+1]@e0+8

    for (int g = 0; g < ngates; g++) {
        // prefetch next gate's W into the other buffer
        if (g + 1 < ngates) {
            const uint4* gw = (const uint4*)&g_W[gbase + g + 1][0];
            uint32_t dst = ((g + 1) & 1) ? sB1 : sB0;
            for (int i = tid; i < 4352; i += 256) cpa16(dst + i * 16, gw + i);
            CP_COMMIT();
        }

        float acc[4][4][4];
        #pragma unroll
        for (int mf = 0; mf < 4; mf++)
            #pragma unroll
            for (int nf = 0; nf < 4; nf++)
                #pragma unroll
                for (int q = 0; q < 4; q++) acc[mf][nf][q] = 0.f;

        const uint32_t sB = ((g & 1) ? sB1 : sB0);

        #pragma unroll
        for (int term = 0; term < 3; term++) {
            const uint32_t aT = aBase + (term == 1 ? (uint32_t)PLANE_A : 0u);
            const uint32_t bT = sB + bRow + (term == 2 ? (uint32_t)PLANE_A : 0u);
            for (int ks = 0; ks < 8; ks++) {
                uint32_t aK = aT + ks * 32;              // +16 cols * 2B
                uint32_t bK = bT + ks * (16 * ROWP * 2); // +16 k-rows
                uint32_t afr[4][4];
                #pragma unroll
                for (int mf = 0; mf < 4; mf++)
                    ldsm_x4(afr[mf], aK + mf * (16 * ROWP * 2));
                uint32_t bfr[4][2];
                #pragma unroll
                for (int nf = 0; nf < 4; nf++)
                    ldsm_x2t(bfr[nf], bK + nf * 16);
                #pragma unroll
                for (int mf = 0; mf < 4; mf++)
                    #pragma unroll
                    for (int nf = 0; nf < 4; nf++)
                        mma16816(acc[mf][nf], afr[mf], bfr[nf]);
            }
        }

        // epilogue
        if (gbase == 4) {
            float* __restrict__ H = g_Ht;
            #pragma unroll
            for (int mf = 0; mf < 4; mf++) {
                int e0 = tile * 128 + wm * 64 + mf * 16 + (lane >> 2);
                #pragma unroll
                for (int nf = 0; nf < 4; nf++) {
                    int d0 = wn * 32 + nf * 8 + (lane & 3) * 2;
                    if (e0 < N_EDGES)
                        *(float2*)&H[e0 * EMB + d0] = make_float2(acc[mf][nf][0], acc[mf][nf][1]);
                    if (e0 + 8 < N_EDGES)
                        *(float2*)&H[(e0 + 8) * EMB + d0] = make_float2(acc[mf][nf][2], acc[mf][nf][3]);
                }
            }
        } else if ((g & 1) == 0) {
            // even gate: pack and hold
            #pragma unroll
            for (int mf = 0; mf < 4; mf++)
                #pragma unroll
                for (int nf = 0; nf < 4; nf++) {
                    hold[(mf * 4 + nf) * 2 + 0] = f2h2(acc[mf][nf][0], acc[mf][nf][1]);
                    hold[(mf * 4 + nf) * 2 + 1] = f2h2(acc[mf][nf][2], acc[mf][nf][3]);
                }
        } else {
            // odd gate: merge with held even gate, coalesced uint2 stores
            uint32_t* __restrict__ P = (g & 2) ? g_P23 : g_P01;
            #pragma unroll
            for (int mf = 0; mf < 4; mf++) {
                int e0 = tile * 128 + wm * 64 + mf * 16 + (lane >> 2);
                #pragma unroll
                for (int nf = 0; nf < 4; nf++) {
                    int d0 = wn * 32 + nf * 8 + (lane & 3) * 2;
                    uint32_t ev0 = hold[(mf * 4 + nf) * 2 + 0];
                    uint32_t ev1 = hold[(mf * 4 + nf) * 2 + 1];
                    uint32_t od0 = f2h2(acc[mf][nf][0], acc[mf][nf][1]);
                    uint32_t od1 = f2h2(acc[mf][nf][2], acc[mf][nf][3]);
                    if (e0 < N_EDGES) {
                        uint2 w = make_uint2(prmt(ev0, od0, 0x5410), prmt(ev0, od0, 0x7632));
                        *(uint2*)&P[e0 * EMB + d0] = w;
                    }
                    if (e0 + 8 < N_EDGES) {
                        uint2 w = make_uint2(prmt(ev1, od1, 0x5410), prmt(ev1, od1, 0x7632));
                        *(uint2*)&P[(e0 + 8) * EMB + d0] = w;
                    }
                }
            }
        }

        if (g + 1 < ngates) {
            CP_WAIT0();
            __syncthreads();   // next buffer ready; all warps done reading current
        }
    }
}

// ---------------------------------------------------------------------------
// Update: gather packed fp16 gate preacts over 6 neighbors + one-hot rows,
// LSTM math (fast activations), write c fp32 + h bf16-split.
// ---------------------------------------------------------------------------
__global__ __launch_bounds__(256) void k_update(
    int cur, int nxt,
    const int* __restrict__ node_ids, const int* __restrict__ edge_src,
    const int* __restrict__ edge_type, const int* __restrict__ bond_list,
    const float* __restrict__ Wi, const float* __restrict__ bi,
    const float* __restrict__ Wo, const float* __restrict__ bo,
    const float* __restrict__ Wf, const float* __restrict__ bf,
    const float* __restrict__ Wu, const float* __restrict__ bu)
{
    __shared__ int s_b[2 * MAX_NB];
    __shared__ int s_nr[2], s_br[2];

    const uint32_t* __restrict__ P01 = g_P01;
    const uint32_t* __restrict__ P23 = g_P23;
    const float* __restrict__ c_old = g_c[cur];
    float* __restrict__ c_new = g_c[nxt];

    const int tid = threadIdx.x;
    const int e0  = blockIdx.x * 2;

    if (tid < 2 * MAX_NB) {
        s_b[tid] = bond_list[e0 * MAX_NB + tid];
    } else if (tid < 2 * MAX_NB + 2) {
        int e = tid - 2 * MAX_NB;
        s_nr[e] = node_ids[edge_src[e0 + e]];
    } else if (tid < 2 * MAX_NB + 4) {
        int e = tid - 2 * MAX_NB - 2;
        s_br[e] = VOCAB + edge_type[e0 + e];
    }
    __syncthreads();

    const int le = tid >> 7;
    const int d  = tid & 127;
    const int e  = e0 + le;

    int b[MAX_NB];
    #pragma unroll
    for (int k = 0; k < MAX_NB; k++) b[k] = s_b[le * MAX_NB + k] * EMB + d;

    // batched independent gathers (high MLP): 18 loads
    uint32_t w01[MAX_NB], w23[MAX_NB];
    float vc[MAX_NB];
    #pragma unroll
    for (int k = 0; k < MAX_NB; k++) {
        w01[k] = P01[b[k]];
        w23[k] = P23[b[k]];
        vc[k]  = c_old[b[k]];
    }

    float si = 0.f, so = 0.f, su = 0.f;
    float vf[MAX_NB];
    #pragma unroll
    for (int k = 0; k < MAX_NB; k++) {
        float2 g01 = __half22float2(*(__half2*)&w01[k]);
        float2 g23 = __half22float2(*(__half2*)&w23[k]);
        si += g01.x;
        so += g01.y;
        su += g23.x;
        vf[k] = g23.y;
    }

    const int nr = s_nr[le], br = s_br[le];
    float i_g = sigfast(si + Wi[nr * EMB + d] + Wi[br * EMB + d] + bi[d]);
    float o_g = sigfast(so + Wo[nr * EMB + d] + Wo[br * EMB + d] + bo[d]);
    float u_g = tanhfast(su + Wu[nr * EMB + d] + Wu[br * EMB + d] + bu[d]);
    float pre_f = Wf[nr * EMB + d] + Wf[br * EMB + d] + bf[d];

    float c_acc = i_g * u_g;
    #pragma unroll
    for (int k = 0; k < MAX_NB; k++)
        c_acc += sigfast(vf[k] + pre_f) * vc[k];

    float h = o_g * tanhfast(c_acc);
    if (e == 0) { h = 0.f; c_acc = 0.f; }
    c_new[e * EMB + d] = c_acc;
    store_h_split(nxt, e, d, h);
}

// ---------------------------------------------------------------------------
// Final node projection: out = relu(Wt[nid] + bt + sum_k Ht[adj[n,k]])
// ---------------------------------------------------------------------------
__global__ __launch_bounds__(256) void k_final(
    const int* __restrict__ node_ids, const int* __restrict__ adj_list,
    const float* __restrict__ Wt, const float* __restrict__ bt,
    float* __restrict__ out)
{
    __shared__ int s_a[2 * MAX_NB];
    __shared__ int s_nid[2];

    const float* __restrict__ Ht = g_Ht;

    const int tid = threadIdx.x;
    const int n0  = blockIdx.x * 2;

    if (tid < 2 * MAX_NB) {
        s_a[tid] = adj_list[n0 * MAX_NB + tid];
    } else if (tid < 2 * MAX_NB + 2) {
        int n = tid - 2 * MAX_NB;
        s_nid[n] = node_ids[n0 + n];
    }
    __syncthreads();

    const int ln = tid >> 7;
    const int d  = tid & 127;
    const int n  = n0 + ln;

    float s = 0.f;
    #pragma unroll
    for (int k = 0; k < MAX_NB; k++)
        s += Ht[s_a[ln * MAX_NB + k] * EMB + d];

    float v = s + Wt[s_nid[ln] * EMB + d] + bt[d];
    v = fmaxf(v, 0.f);
    if (n == 0) v = 0.f;
    out[n * EMB + d] = v;
}

// ---------------------------------------------------------------------------
extern "C" void kernel_launch(void* const* d_in, const int* in_sizes, int n_in,
                              void* d_out, int out_size)
{
    const int*   node_ids  = (const int*)d_in[0];
    const int*   edge_src  = (const int*)d_in[1];
    const int*   edge_type = (const int*)d_in[2];
    const int*   adj_list  = (const int*)d_in[3];
    const int*   bond_list = (const int*)d_in[4];
    const float* Wi = (const float*)d_in[5];
    const float* bi = (const float*)d_in[6];
    const float* Wo = (const float*)d_in[7];
    const float* bo = (const float*)d_in[8];
    const float* Wf = (const float*)d_in[9];
    const float* bf = (const float*)d_in[10];
    const float* Wu = (const float*)d_in[11];
    const float* bu = (const float*)d_in[12];
    const float* Wt = (const float*)d_in[13];
    const float* bt = (const float*)d_in[14];
    float* out = (float*)d_out;

    cudaFuncSetAttribute(k_mma, cudaFuncAttributeMaxDynamicSharedMemorySize, MMA_SMEM);

    k_prep<<<5, 256>>>(Wi, Wo, Wu, Wf, Wt);
    k_depth0<<<(N_EDGES * EMB) / 256, 256>>>(node_ids, edge_src, edge_type,
                                             Wi, bi, Wo, bo, Wu, bu);

    int cur = 0, nxt = 1;
    for (int depth = 1; depth < 4; depth++) {
        k_mma<<<NT, 256, MMA_SMEM>>>(cur, 0, 4);
        k_update<<<N_EDGES / 2, 256>>>(cur, nxt, node_ids, edge_src, edge_type,
                                       bond_list, Wi, bi, Wo, bo, Wf, bf, Wu, bu);
        int t = cur; cur = nxt; nxt = t;
    }

    k_mma<<<NT, 256, MMA_SMEM>>>(cur, 4, 1);   // Ht -> g_Ht (fp32)
    k_final<<<N_NODES / 2, 256>>>(node_ids, adj_list, Wt, bt, out);
}

// round 9
// speedup vs baseline: 3.6632x; 1.0409x over previous
#include <cuda_runtime.h>
#include <cuda_bf16.h>
#include <cuda_fp16.h>
#include <math.h>
#include <stdint.h>

#define VOCAB   100
#define NBOND   4
#define EMB     128
#define N_NODES 25000
#define N_EDGES 50000
#define MAX_NB  6
#define HOFF    104
#define NT      391              // ceil(50000/128) edge tiles
#define PAD_E   (NT * 128)       // 50048
#define ROWP    136              // padded row length (bf16 elems) -> 272B rows
#define PLANE_A 34816            // 128*ROWP*2 bytes, one 128-row bf16 plane
#define WELEMS  17408            // 128*ROWP elems per W plane

// ---------------- static device scratch (no allocation) ----------------
__device__ float g_c[2][N_EDGES * EMB];                  // cell state ping-pong
// interleaved gate preacts: per (e, dpair): {io(d), io(d+1), uf(d), uf(d+1)} as 4x half2
__device__ uint4 g_P4[N_EDGES * (EMB / 2)];
__device__ float g_Ht[N_EDGES * EMB];                    // final-pass fp32 Ht
__device__ __align__(16) __nv_bfloat16 g_hb[2][2][PAD_E * ROWP]; // h hi/lo planes, padded rows
__device__ __align__(16) __nv_bfloat16 g_W[5][2 * WELEMS];       // W[k][d] hi/lo, padded rows

// fast activations: tanh.approx.f32 (sm_75+ baseline PTX)
__device__ __forceinline__ float tanhfast(float x) {
    float y;
    asm("tanh.approx.f32 %0, %1;" : "=f"(y) : "f"(x));
    return y;
}
__device__ __forceinline__ float sigfast(float x) {
    return fmaf(0.5f, tanhfast(0.5f * x), 0.5f);
}

__device__ __forceinline__ uint32_t smem_u32(const void* p) {
    uint32_t a;
    asm("{ .reg .u64 t; cvta.to.shared.u64 t, %1; cvt.u32.u64 %0, t; }" : "=r"(a) : "l"(p));
    return a;
}
__device__ __forceinline__ void cpa16(uint32_t s, const void* g) {
    asm volatile("cp.async.cg.shared.global [%0], [%1], 16;" :: "r"(s), "l"(g) : "memory");
}
#define CP_COMMIT() asm volatile("cp.async.commit_group;" ::: "memory")
#define CP_WAIT0()  asm volatile("cp.async.wait_group 0;" ::: "memory")

__device__ __forceinline__ void ldsm_x4(uint32_t* r, uint32_t addr) {
    asm volatile("ldmatrix.sync.aligned.m8n8.x4.shared.b16 {%0,%1,%2,%3}, [%4];"
                 : "=r"(r[0]), "=r"(r[1]), "=r"(r[2]), "=r"(r[3]) : "r"(addr));
}
__device__ __forceinline__ void ldsm_x2t(uint32_t* r, uint32_t addr) {
    asm volatile("ldmatrix.sync.aligned.m8n8.x2.trans.shared.b16 {%0,%1}, [%2];"
                 : "=r"(r[0]), "=r"(r[1]) : "r"(addr));
}
__device__ __forceinline__ void mma16816(float* c, const uint32_t* a, const uint32_t* b) {
    asm volatile("mma.sync.aligned.m16n8k16.row.col.f32.bf16.bf16.f32 "
                 "{%0,%1,%2,%3}, {%4,%5,%6,%7}, {%8,%9}, {%0,%1,%2,%3};"
                 : "+f"(c[0]), "+f"(c[1]), "+f"(c[2]), "+f"(c[3])
                 : "r"(a[0]), "r"(a[1]), "r"(a[2]), "r"(a[3]), "r"(b[0]), "r"(b[1]));
}
__device__ __forceinline__ uint32_t prmt(uint32_t a, uint32_t b, uint32_t s) {
    uint32_t d;
    asm("prmt.b32 %0, %1, %2, %3;" : "=r"(d) : "r"(a), "r"(b), "r"(s));
    return d;
}
__device__ __forceinline__ uint32_t f2h2(float a, float b) {
    __half2 h = __floats2half2_rn(a, b);   // low = a
    return *(uint32_t*)&h;
}

// write (e, d0) and (e, d0+1) h values as bf16 hi/lo (d0 even -> 4B stores)
__device__ __forceinline__ void store_h_split2(int buf, int e, int d0, float h0, float h1) {
    __nv_bfloat162 hi = __floats2bfloat162_rn(h0, h1);   // low = h0
    float l0 = h0 - __bfloat162float(__low2bfloat16(hi));
    float l1 = h1 - __bfloat162float(__high2bfloat16(hi));
    __nv_bfloat162 lo = __floats2bfloat162_rn(l0, l1);
    *(uint32_t*)&g_hb[buf][0][e * ROWP + d0] = *(uint32_t*)&hi;
    *(uint32_t*)&g_hb[buf][1][e * ROWP + d0] = *(uint32_t*)&lo;
}

// ---------------------------------------------------------------------------
// Prep: W hi/lo planes, rows k = 0..127 (source rows roff+k), padded to ROWP
// ---------------------------------------------------------------------------
__global__ __launch_bounds__(256) void k_prep(
    const float* __restrict__ Wi, const float* __restrict__ Wo,
    const float* __restrict__ Wu, const float* __restrict__ Wf,
    const float* __restrict__ Wt)
{
    int g = blockIdx.x;
    const float* W;
    int roff;
    switch (g) {
        case 0: W = Wi; roff = HOFF; break;
        case 1: W = Wo; roff = HOFF; break;
        case 2: W = Wu; roff = HOFF; break;
        case 3: W = Wf; roff = HOFF; break;
        default: W = Wt; roff = VOCAB; break;
    }
    for (int idx = threadIdx.x; idx < 16384; idx += 256) {
        int k = idx >> 7;
        int d = idx & 127;
        float v = W[(roff + k) * EMB + d];
        __nv_bfloat16 hi = __float2bfloat16(v);
        g_W[g][k * ROWP + d] = hi;
        g_W[g][WELEMS + k * ROWP + d] = __float2bfloat16(v - __bfloat162float(hi));
    }
}

// ---------------------------------------------------------------------------
// Depth 0: one-hot gather + activations; writes c fp32 + h bf16-split
// ---------------------------------------------------------------------------
__global__ __launch_bounds__(256) void k_depth0(
    const int* __restrict__ node_ids, const int* __restrict__ edge_src,
    const int* __restrict__ edge_type,
    const float* __restrict__ Wi, const float* __restrict__ bi,
    const float* __restrict__ Wo, const float* __restrict__ bo,
    const float* __restrict__ Wu, const float* __restrict__ bu)
{
    int gidx = blockIdx.x * blockDim.x + threadIdx.x;   // e*64 + dh
    int e = gidx >> 6, dh = gidx & 63;
    int d0 = dh * 2;
    int nrow = node_ids[edge_src[e]];
    int brow = VOCAB + edge_type[e];

    float2 win = *(const float2*)&Wi[nrow * EMB + d0];
    float2 wib = *(const float2*)&Wi[brow * EMB + d0];
    float2 bi2 = *(const float2*)&bi[d0];
    float2 won = *(const float2*)&Wo[nrow * EMB + d0];
    float2 wob = *(const float2*)&Wo[brow * EMB + d0];
    float2 bo2 = *(const float2*)&bo[d0];
    float2 wun = *(const float2*)&Wu[nrow * EMB + d0];
    float2 wub = *(const float2*)&Wu[brow * EMB + d0];
    float2 bu2 = *(const float2*)&bu[d0];

    float h[2], c[2];
    #pragma unroll
    for (int q = 0; q < 2; q++) {
        float pi = (q ? win.y + wib.y + bi2.y : win.x + wib.x + bi2.x);
        float po = (q ? won.y + wob.y + bo2.y : won.x + wob.x + bo2.x);
        float pu = (q ? wun.y + wub.y + bu2.y : wun.x + wub.x + bu2.x);
        float i = sigfast(pi), o = sigfast(po), u = tanhfast(pu);
        c[q] = i * u;
        h[q] = o * tanhfast(c[q]);
        if (e == 0) { h[q] = 0.0f; c[q] = 0.0f; }
    }
    *(float2*)&g_c[0][e * EMB + d0] = make_float2(c[0], c[1]);
    store_h_split2(0, e, d0, h[0], h[1]);
}

// ---------------------------------------------------------------------------
// Tensor-core GEMM via mma.sync bf16-split. Gate passes (gbase=0, ngates=4):
// gates processed in pairs; even gate held as packed halves, merged with the
// odd gate via prmt. Pair (0,1) -> .xy of g_P4 word, pair (2,3) -> .zw.
// Final pass (gbase=4, ngates=1): fp32 into g_Ht.
// ---------------------------------------------------------------------------
#define MMA_SMEM (3 * 2 * PLANE_A)   // A(hi+lo) + 2 W buffers (hi+lo) = 208896 B

__global__ __launch_bounds__(256) void k_mma(int cur, int gbase, int ngates)
{
    extern __shared__ __align__(16) char sm[];
    const int tid  = threadIdx.x;
    const int lane = tid & 31;
    const int wid  = tid >> 5;
    const int wm   = wid >> 2;     // 0..1  -> edge offset wm*64
    const int wn   = wid & 3;      // 0..3  -> dim  offset wn*32
    const int tile = blockIdx.x;

    const uint32_t sA  = smem_u32(sm);
    const uint32_t sB0 = sA + 2 * PLANE_A;
    const uint32_t sB1 = sA + 4 * PLANE_A;

    // stage A hi/lo (two planes) + first W (hi+lo contiguous) via cp.async
    {
        const uint4* gAhi = (const uint4*)&g_hb[cur][0][(size_t)tile * 128 * ROWP];
        const uint4* gAlo = (const uint4*)&g_hb[cur][1][(size_t)tile * 128 * ROWP];
        const uint4* gW0  = (const uint4*)&g_W[gbase][0];
        for (int i = tid; i < 2176; i += 256) cpa16(sA + i * 16, gAhi + i);
        for (int i = tid; i < 2176; i += 256) cpa16(sA + PLANE_A + i * 16, gAlo + i);
        for (int i = tid; i < 4352; i += 256) cpa16(sB0 + i * 16, gW0 + i);
        CP_COMMIT();
        CP_WAIT0();
    }
    __syncthreads();

    // per-thread ldmatrix base addresses
    const uint32_t aBase = sA + (uint32_t)((wm * 64 + (lane & 15)) * ROWP + ((lane & 16) ? 8 : 0)) * 2;
    const uint32_t bRow  = (uint32_t)((lane & 15) * ROWP + wn * 32) * 2;

    uint32_t hold[32];   // even gate's halves: per (mf,nf): [d0,d0+1]@e0, [d0,d0+1]@e0+8

    for (int g = 0; g < ngates; g++) {
        // prefetch next gate's W into the other buffer
        if (g + 1 < ngates) {
            const uint4* gw = (const uint4*)&g_W[gbase + g + 1][0];
            uint32_t dst = ((g + 1) & 1) ? sB1 : sB0;
            for (int i = tid; i < 4352; i += 256) cpa16(dst + i * 16, gw + i);
            CP_COMMIT();
        }

        float acc[4][4][4];
        #pragma unroll
        for (int mf = 0; mf < 4; mf++)
            #pragma unroll
            for (int nf = 0; nf < 4; nf++)
                #pragma unroll
                for (int q = 0; q < 4; q++) acc[mf][nf][q] = 0.f;

        const uint32_t sB = ((g & 1) ? sB1 : sB0);

        #pragma unroll
        for (int term = 0; term < 3; term++) {
            const uint32_t aT = aBase + (term == 1 ? (uint32_t)PLANE_A : 0u);
            const uint32_t bT = sB + bRow + (term == 2 ? (uint32_t)PLANE_A : 0u);
            for (int ks = 0; ks < 8; ks++) {
                uint32_t aK = aT + ks * 32;              // +16 cols * 2B
                uint32_t bK = bT + ks * (16 * ROWP * 2); // +16 k-rows
                uint32_t afr[4][4];
                #pragma unroll
                for (int mf = 0; mf < 4; mf++)
                    ldsm_x4(afr[mf], aK + mf * (16 * ROWP * 2));
                uint32_t bfr[4][2];
                #pragma unroll
                for (int nf = 0; nf < 4; nf++)
                    ldsm_x2t(bfr[nf], bK + nf * 16);
                #pragma unroll
                for (int mf = 0; mf < 4; mf++)
                    #pragma unroll
                    for (int nf = 0; nf < 4; nf++)
                        mma16816(acc[mf][nf], afr[mf], bfr[nf]);
            }
        }

        // epilogue
        if (gbase == 4) {
            float* __restrict__ H = g_Ht;
            #pragma unroll
            for (int mf = 0; mf < 4; mf++) {
                int e0 = tile * 128 + wm * 64 + mf * 16 + (lane >> 2);
                #pragma unroll
                for (int nf = 0; nf < 4; nf++) {
                    int d0 = wn * 32 + nf * 8 + (lane & 3) * 2;
                    if (e0 < N_EDGES)
                        *(float2*)&H[e0 * EMB + d0] = make_float2(acc[mf][nf][0], acc[mf][nf][1]);
                    if (e0 + 8 < N_EDGES)
                        *(float2*)&H[(e0 + 8) * EMB + d0] = make_float2(acc[mf][nf][2], acc[mf][nf][3]);
                }
            }
        } else if ((g & 1) == 0) {
            // even gate: pack and hold
            #pragma unroll
            for (int mf = 0; mf < 4; mf++)
                #pragma unroll
                for (int nf = 0; nf < 4; nf++) {
                    hold[(mf * 4 + nf) * 2 + 0] = f2h2(acc[mf][nf][0], acc[mf][nf][1]);
                    hold[(mf * 4 + nf) * 2 + 1] = f2h2(acc[mf][nf][2], acc[mf][nf][3]);
                }
        } else {
            // odd gate: merge with held even gate; pair (0,1)->.xy, (2,3)->.zw
            const int zoff = (g & 2) ? 2 : 0;   // uint offset within uint4 word
            uint32_t* __restrict__ P = (uint32_t*)g_P4;
            #pragma unroll
            for (int mf = 0; mf < 4; mf++) {
                int e0 = tile * 128 + wm * 64 + mf * 16 + (lane >> 2);
                #pragma unroll
                for (int nf = 0; nf < 4; nf++) {
                    int d0 = wn * 32 + nf * 8 + (lane & 3) * 2;
                    uint32_t ev0 = hold[(mf * 4 + nf) * 2 + 0];
                    uint32_t ev1 = hold[(mf * 4 + nf) * 2 + 1];
                    uint32_t od0 = f2h2(acc[mf][nf][0], acc[mf][nf][1]);
                    uint32_t od1 = f2h2(acc[mf][nf][2], acc[mf][nf][3]);
                    if (e0 < N_EDGES) {
                        uint2 w = make_uint2(prmt(ev0, od0, 0x5410), prmt(ev0, od0, 0x7632));
                        *(uint2*)&P[(e0 * 64 + (d0 >> 1)) * 4 + zoff] = w;
                    }
                    if (e0 + 8 < N_EDGES) {
                        uint2 w = make_uint2(prmt(ev1, od1, 0x5410), prmt(ev1, od1, 0x7632));
                        *(uint2*)&P[((e0 + 8) * 64 + (d0 >> 1)) * 4 + zoff] = w;
                    }
                }
            }
        }

        if (g + 1 < ngates) {
            CP_WAIT0();
            __syncthreads();   // next buffer ready; all warps done reading current
        }
    }
}

// ---------------------------------------------------------------------------
// Update: per neighbor ONE 16B gather (all 4 gates, 2 dims) + ONE 8B c gather.
// 4 edges per 256-thread block; 64 threads x 2 dims per edge.
// ---------------------------------------------------------------------------
__global__ __launch_bounds__(256) void k_update(
    int cur, int nxt,
    const int* __restrict__ node_ids, const int* __restrict__ edge_src,
    const int* __restrict__ edge_type, const int* __restrict__ bond_list,
    const float* __restrict__ Wi, const float* __restrict__ bi,
    const float* __restrict__ Wo, const float* __restrict__ bo,
    const float* __restrict__ Wf, const float* __restrict__ bf,
    const float* __restrict__ Wu, const float* __restrict__ bu)
{
    __shared__ int s_b[4 * MAX_NB];
    __shared__ int s_nr[4], s_br[4];

    const uint4* __restrict__ P4 = g_P4;
    const float* __restrict__ c_old = g_c[cur];
    float* __restrict__ c_new = g_c[nxt];

    const int tid = threadIdx.x;
    const int e0  = blockIdx.x * 4;

    if (tid < 4 * MAX_NB) {
        s_b[tid] = bond_list[e0 * MAX_NB + tid];
    } else if (tid < 4 * MAX_NB + 4) {
        int e = tid - 4 * MAX_NB;
        s_nr[e] = node_ids[edge_src[e0 + e]];
    } else if (tid < 4 * MAX_NB + 8) {
        int e = tid - 4 * MAX_NB - 4;
        s_br[e] = VOCAB + edge_type[e0 + e];
    }
    __syncthreads();

    const int le = tid >> 6;        // local edge 0..3
    const int dh = tid & 63;        // dim pair index
    const int d0 = dh * 2;
    const int e  = e0 + le;

    int b[MAX_NB];
    #pragma unroll
    for (int k = 0; k < MAX_NB; k++) b[k] = s_b[le * MAX_NB + k];

    // batched independent gathers: 6x16B + 6x8B
    uint4  p[MAX_NB];
    float2 vc[MAX_NB];
    #pragma unroll
    for (int k = 0; k < MAX_NB; k++) {
        p[k]  = P4[b[k] * 64 + dh];
        vc[k] = *(const float2*)&c_old[b[k] * EMB + d0];
    }

    float si[2] = {0.f, 0.f}, so[2] = {0.f, 0.f}, su[2] = {0.f, 0.f};
    float vf[2][MAX_NB];
    #pragma unroll
    for (int k = 0; k < MAX_NB; k++) {
        float2 io0 = __half22float2(*(__half2*)&p[k].x);   // (i,o)@d0
        float2 io1 = __half22float2(*(__half2*)&p[k].y);   // (i,o)@d0+1
        float2 uf0 = __half22float2(*(__half2*)&p[k].z);   // (u,f)@d0
        float2 uf1 = __half22float2(*(__half2*)&p[k].w);   // (u,f)@d0+1
        si[0] += io0.x; so[0] += io0.y; su[0] += uf0.x; vf[0][k] = uf0.y;
        si[1] += io1.x; so[1] += io1.y; su[1] += uf1.x; vf[1][k] = uf1.y;
    }

    const int nr = s_nr[le], br = s_br[le];
    float2 win = *(const float2*)&Wi[nr * EMB + d0];
    float2 wib = *(const float2*)&Wi[br * EMB + d0];
    float2 bi2 = *(const float2*)&bi[d0];
    float2 won = *(const float2*)&Wo[nr * EMB + d0];
    float2 wob = *(const float2*)&Wo[br * EMB + d0];
    float2 bo2 = *(const float2*)&bo[d0];
    float2 wun = *(const float2*)&Wu[nr * EMB + d0];
    float2 wub = *(const float2*)&Wu[br * EMB + d0];
    float2 bu2 = *(const float2*)&bu[d0];
    float2 wfn = *(const float2*)&Wf[nr * EMB + d0];
    float2 wfb = *(const float2*)&Wf[br * EMB + d0];
    float2 bf2 = *(const float2*)&bf[d0];

    float h[2], c[2];
    #pragma unroll
    for (int q = 0; q < 2; q++) {
        float i_g = sigfast(si[q] + (q ? win.y + wib.y + bi2.y : win.x + wib.x + bi2.x));
        float o_g = sigfast(so[q] + (q ? won.y + wob.y + bo2.y : won.x + wob.x + bo2.x));
        float u_g = tanhfast(su[q] + (q ? wun.y + wub.y + bu2.y : wun.x + wub.x + bu2.x));
        float pre_f = (q ? wfn.y + wfb.y + bf2.y : wfn.x + wfb.x + bf2.x);

        float c_acc = i_g * u_g;
        #pragma unroll
        for (int k = 0; k < MAX_NB; k++)
            c_acc += sigfast(vf[q][k] + pre_f) * (q ? vc[k].y : vc[k].x);

        h[q] = o_g * tanhfast(c_acc);
        c[q] = c_acc;
        if (e == 0) { h[q] = 0.f; c[q] = 0.f; }
    }

    *(float2*)&c_new[e * EMB + d0] = make_float2(c[0], c[1]);
    store_h_split2(nxt, e, d0, h[0], h[1]);
}

// ---------------------------------------------------------------------------
// Final node projection: out = relu(Wt[nid] + bt + sum_k Ht[adj[n,k]])
// ---------------------------------------------------------------------------
__global__ __launch_bounds__(256) void k_final(
    const int* __restrict__ node_ids, const int* __restrict__ adj_list,
    const float* __restrict__ Wt, const float* __restrict__ bt,
    float* __restrict__ out)
{
    __shared__ int s_a[2 * MAX_NB];
    __shared__ int s_nid[2];

    const float* __restrict__ Ht = g_Ht;

    const int tid = threadIdx.x;
    const int n0  = blockIdx.x * 2;

    if (tid < 2 * MAX_NB) {
        s_a[tid] = adj_list[n0 * MAX_NB + tid];
    } else if (tid < 2 * MAX_NB + 2) {
        int n = tid - 2 * MAX_NB;
        s_nid[n] = node_ids[n0 + n];
    }
    __syncthreads();

    const int ln = tid >> 7;
    const int d  = tid & 127;
    const int n  = n0 + ln;

    float s = 0.f;
    #pragma unroll
    for (int k = 0; k < MAX_NB; k++)
        s += Ht[s_a[ln * MAX_NB + k] * EMB + d];

    float v = s + Wt[s_nid[ln] * EMB + d] + bt[d];
    v = fmaxf(v, 0.f);
    if (n == 0) v = 0.f;
    out[n * EMB + d] = v;
}

// ---------------------------------------------------------------------------
extern "C" void kernel_launch(void* const* d_in, const int* in_sizes, int n_in,
                              void* d_out, int out_size)
{
    const int*   node_ids  = (const int*)d_in[0];
    const int*   edge_src  = (const int*)d_in[1];
    const int*   edge_type = (const int*)d_in[2];
    const int*   adj_list  = (const int*)d_in[3];
    const int*   bond_list = (const int*)d_in[4];
    const float* Wi = (const float*)d_in[5];
    const float* bi = (const float*)d_in[6];
    const float* Wo = (const float*)d_in[7];
    const float* bo = (const float*)d_in[8];
    const float* Wf = (const float*)d_in[9];
    const float* bf = (const float*)d_in[10];
    const float* Wu = (const float*)d_in[11];
    const float* bu = (const float*)d_in[12];
    const float* Wt = (const float*)d_in[13];
    const float* bt = (const float*)d_in[14];
    float* out = (float*)d_out;

    cudaFuncSetAttribute(k_mma, cudaFuncAttributeMaxDynamicSharedMemorySize, MMA_SMEM);

    k_prep<<<5, 256>>>(Wi, Wo, Wu, Wf, Wt);
    k_depth0<<<(N_EDGES * 64) / 256, 256>>>(node_ids, edge_src, edge_type,
                                            Wi, bi, Wo, bo, Wu, bu);

    int cur = 0, nxt = 1;
    for (int depth = 1; depth < 4; depth++) {
        k_mma<<<NT, 256, MMA_SMEM>>>(cur, 0, 4);
        k_update<<<N_EDGES / 4, 256>>>(cur, nxt, node_ids, edge_src, edge_type,
                                       bond_list, Wi, bi, Wo, bo, Wf, bf, Wu, bu);
        int t = cur; cur = nxt; nxt = t;
    }

    k_mma<<<NT, 256, MMA_SMEM>>>(cur, 4, 1);   // Ht -> g_Ht (fp32)
    k_final<<<N_NODES / 2, 256>>>(node_ids, adj_list, Wt, bt, out);
}

// round 12
// speedup vs baseline: 5.3241x; 1.4534x over previous
#include <cuda_runtime.h>
#include <cuda_fp16.h>
#include <math.h>
#include <stdint.h>

#define VOCAB   100
#define NBOND   4
#define EMB     128
#define N_NODES 25000
#define N_EDGES 50000
#define MAX_NB  6
#define HOFF    104
#define NT      391              // ceil(50000/128) edge tiles
#define PAD_E   (NT * 128)       // 50048
#define ROWP    136              // padded row length (fp16 elems) -> 272B rows
#define PLANE_A 34816            // 128*ROWP*2 bytes, one 128-row fp16 plane
#define WELEMS  17408            // 128*ROWP elems per W plane

// ---------------- static device scratch (no allocation) ----------------
__device__ float g_c[2][N_EDGES * EMB];                  // cell state ping-pong
// interleaved gate preacts: per (e, dpair): {io(d), io(d+1), uf(d), uf(d+1)} as 4x half2
__device__ uint4 g_P4[N_EDGES * (EMB / 2)];
__device__ float g_Ht[N_EDGES * EMB];                    // final-pass fp32 Ht
__device__ __align__(16) __half g_hb[2][PAD_E * ROWP];   // h fp16 planes (ping-pong), padded rows
__device__ __align__(16) __half g_W[5][WELEMS];          // W[k][d] fp16, padded rows

// fast activations: tanh.approx.f32 (sm_75+ baseline PTX)
__device__ __forceinline__ float tanhfast(float x) {
    float y;
    asm("tanh.approx.f32 %0, %1;" : "=f"(y) : "f"(x));
    return y;
}
__device__ __forceinline__ float sigfast(float x) {
    return fmaf(0.5f, tanhfast(0.5f * x), 0.5f);
}

__device__ __forceinline__ uint32_t smem_u32(const void* p) {
    uint32_t a;
    asm("{ .reg .u64 t; cvta.to.shared.u64 t, %1; cvt.u32.u64 %0, t; }" : "=r"(a) : "l"(p));
    return a;
}
__device__ __forceinline__ void cpa16(uint32_t s, const void* g) {
    asm volatile("cp.async.cg.shared.global [%0], [%1], 16;" :: "r"(s), "l"(g) : "memory");
}
#define CP_COMMIT() asm volatile("cp.async.commit_group;" ::: "memory")
#define CP_WAIT0()  asm volatile("cp.async.wait_group 0;" ::: "memory")

__device__ __forceinline__ void ldsm_x4(uint32_t* r, uint32_t addr) {
    asm volatile("ldmatrix.sync.aligned.m8n8.x4.shared.b16 {%0,%1,%2,%3}, [%4];"
                 : "=r"(r[0]), "=r"(r[1]), "=r"(r[2]), "=r"(r[3]) : "r"(addr));
}
__device__ __forceinline__ void ldsm_x2t(uint32_t* r, uint32_t addr) {
    asm volatile("ldmatrix.sync.aligned.m8n8.x2.trans.shared.b16 {%0,%1}, [%2];"
                 : "=r"(r[0]), "=r"(r[1]) : "r"(addr));
}
// fp16 inputs, fp32 accumulate
__device__ __forceinline__ void mma16816(float* c, const uint32_t* a, const uint32_t* b) {
    asm volatile("mma.sync.aligned.m16n8k16.row.col.f32.f16.f16.f32 "
                 "{%0,%1,%2,%3}, {%4,%5,%6,%7}, {%8,%9}, {%0,%1,%2,%3};"
                 : "+f"(c[0]), "+f"(c[1]), "+f"(c[2]), "+f"(c[3])
                 : "r"(a[0]), "r"(a[1]), "r"(a[2]), "r"(a[3]), "r"(b[0]), "r"(b[1]));
}
__device__ __forceinline__ uint32_t prmt(uint32_t a, uint32_t b, uint32_t s) {
    uint32_t d;
    asm("prmt.b32 %0, %1, %2, %3;" : "=r"(d) : "r"(a), "r"(b), "r"(s));
    return d;
}
__device__ __forceinline__ uint32_t f2h2(float a, float b) {
    __half2 h = __floats2half2_rn(a, b);   // low = a
    return *(uint32_t*)&h;
}

// write (e, d0) and (e, d0+1) h values as one fp16x2 (4B) store
__device__ __forceinline__ void store_h2(int buf, int e, int d0, float h0, float h1) {
    *(uint32_t*)&g_hb[buf][e * ROWP + d0] = f2h2(h0, h1);
}

// ---------------------------------------------------------------------------
// Prep: W fp16 planes, rows k = 0..127 (source rows roff+k), padded to ROWP
// ---------------------------------------------------------------------------
__global__ __launch_bounds__(256) void k_prep(
    const float* __restrict__ Wi, const float* __restrict__ Wo,
    const float* __restrict__ Wu, const float* __restrict__ Wf,
    const float* __restrict__ Wt)
{
    int g = blockIdx.x;
    const float* W;
    int roff;
    switch (g) {
        case 0: W = Wi; roff = HOFF; break;
        case 1: W = Wo; roff = HOFF; break;
        case 2: W = Wu; roff = HOFF; break;
        case 3: W = Wf; roff = HOFF; break;
        default: W = Wt; roff = VOCAB; break;
    }
    for (int idx = threadIdx.x; idx < 16384; idx += 256) {
        int k = idx >> 7;
        int d = idx & 127;
        g_W[g][k * ROWP + d] = __float2half_rn(W[(roff + k) * EMB + d]);
    }
}

// ---------------------------------------------------------------------------
// Depth 0: one-hot gather + activations; writes c fp32 + h fp16
// ---------------------------------------------------------------------------
__global__ __launch_bounds__(256) void k_depth0(
    const int* __restrict__ node_ids, const int* __restrict__ edge_src,
    const int* __restrict__ edge_type,
    const float* __restrict__ Wi, const float* __restrict__ bi,
    const float* __restrict__ Wo, const float* __restrict__ bo,
    const float* __restrict__ Wu, const float* __restrict__ bu)
{
    int gidx = blockIdx.x * blockDim.x + threadIdx.x;   // e*64 + dh
    int e = gidx >> 6, dh = gidx & 63;
    int d0 = dh * 2;
    int nrow = node_ids[edge_src[e]];
    int brow = VOCAB + edge_type[e];

    float2 win = *(const float2*)&Wi[nrow * EMB + d0];
    float2 wib = *(const float2*)&Wi[brow * EMB + d0];
    float2 bi2 = *(const float2*)&bi[d0];
    float2 won = *(const float2*)&Wo[nrow * EMB + d0];
    float2 wob = *(const float2*)&Wo[brow * EMB + d0];
    float2 bo2 = *(const float2*)&bo[d0];
    float2 wun = *(const float2*)&Wu[nrow * EMB + d0];
    float2 wub = *(const float2*)&Wu[brow * EMB + d0];
    float2 bu2 = *(const float2*)&bu[d0];

    float h[2], c[2];
    #pragma unroll
    for (int q = 0; q < 2; q++) {
        float pi = (q ? win.y + wib.y + bi2.y : win.x + wib.x + bi2.x);
        float po = (q ? won.y + wob.y + bo2.y : won.x + wob.x + bo2.x);
        float pu = (q ? wun.y + wub.y + bu2.y : wun.x + wub.x + bu2.x);
        float i = sigfast(pi), o = sigfast(po), u = tanhfast(pu);
        c[q] = i * u;
        h[q] = o * tanhfast(c[q]);
        if (e == 0) { h[q] = 0.0f; c[q] = 0.0f; }
    }
    *(float2*)&g_c[0][e * EMB + d0] = make_float2(c[0], c[1]);
    store_h2(0, e, d0, h[0], h[1]);
}

// ---------------------------------------------------------------------------
// Tensor-core GEMM via mma.sync fp16 (single term, fp32 accum).
// Gate passes (gbase=0, ngates=4): gates in pairs; even gate held as packed
// halves, merged with the odd gate via prmt into g_P4 components.
// Final pass (gbase=4, ngates=1): fp32 into g_Ht.
// SMEM: A 34KB + 2 W buffers 68KB = 102KB -> 2 CTAs/SM.
// ---------------------------------------------------------------------------
#define MMA_SMEM (3 * PLANE_A)   // 104448 B

__global__ __launch_bounds__(256) void k_mma(int cur, int gbase, int ngates)
{
    extern __shared__ __align__(16) char sm[];
    const int tid  = threadIdx.x;
    const int lane = tid & 31;
    const int wid  = tid >> 5;
    const int wm   = wid >> 2;     // 0..1  -> edge offset wm*64
    const int wn   = wid & 3;      // 0..3  -> dim  offset wn*32
    const int tile = blockIdx.x;

    const uint32_t sA  = smem_u32(sm);
    const uint32_t sB0 = sA + PLANE_A;
    const uint32_t sB1 = sA + 2 * PLANE_A;

    // stage A (h tile) + first W via cp.async
    {
        const uint4* gA = (const uint4*)&g_hb[cur][(size_t)tile * 128 * ROWP];
        const uint4* gW0 = (const uint4*)&g_W[gbase][0];
        for (int i = tid; i < 2176; i += 256) cpa16(sA + i * 16, gA + i);
        for (int i = tid; i < 2176; i += 256) cpa16(sB0 + i * 16, gW0 + i);
        CP_COMMIT();
        CP_WAIT0();
    }
    __syncthreads();

    // per-thread ldmatrix base addresses
    const uint32_t aBase = sA + (uint32_t)((wm * 64 + (lane & 15)) * ROWP + ((lane & 16) ? 8 : 0)) * 2;
    const uint32_t bRow  = (uint32_t)((lane & 15) * ROWP + wn * 32) * 2;

    uint32_t hold[32];   // even gate's halves: per (mf,nf): [d0,d0+1]@e0, [d0,d0+1]@e0+8

    for (int g = 0; g < ngates; g++) {
        // prefetch next gate's W into the other buffer
        if (g + 1 < ngates) {
            const uint4* gw = (const uint4*)&g_W[gbase + g + 1][0];
            uint32_t dst = ((g + 1) & 1) ? sB1 : sB0;
            for (int i = tid; i < 2176; i += 256) cpa16(dst + i * 16, gw + i);
            CP_COMMIT();
        }

        float acc[4][4][4];
        #pragma unroll
        for (int mf = 0; mf < 4; mf++)
            #pragma unroll
            for (int nf = 0; nf < 4; nf++)
                #pragma unroll
                for (int q = 0; q < 4; q++) acc[mf][nf][q] = 0.f;

        const uint32_t sB = ((g & 1) ? sB1 : sB0) + bRow;

        #pragma unroll
        for (int ks = 0; ks < 8; ks++) {
            uint32_t aK = aBase + ks * 32;           // +16 cols * 2B
            uint32_t bK = sB + ks * (16 * ROWP * 2); // +16 k-rows
            uint32_t afr[4][4];
            #pragma unroll
            for (int mf = 0; mf < 4; mf++)
                ldsm_x4(afr[mf], aK + mf * (16 * ROWP * 2));
            uint32_t bfr[4][2];
            #pragma unroll
            for (int nf = 0; nf < 4; nf++)
                ldsm_x2t(bfr[nf], bK + nf * 16);
            #pragma unroll
            for (int mf = 0; mf < 4; mf++)
                #pragma unroll
                for (int nf = 0; nf < 4; nf++)
                    mma16816(acc[mf][nf], afr[mf], bfr[nf]);
        }

        // epilogue
        if (gbase == 4) {
            float* __restrict__ H = g_Ht;
            #pragma unroll
            for (int mf = 0; mf < 4; mf++) {
                int e0 = tile * 128 + wm * 64 + mf * 16 + (lane >> 2);
                #pragma unroll
                for (int nf = 0; nf < 4; nf++) {
                    int d0 = wn * 32 + nf * 8 + (lane & 3) * 2;
                    if (e0 < N_EDGES)
                        *(float2*)&H[e0 * EMB + d0] = make_float2(acc[mf][nf][0], acc[mf][nf][1]);
                    if (e0 + 8 < N_EDGES)
                        *(float2*)&H[(e0 + 8) * EMB + d0] = make_float2(acc[mf][nf][2], acc[mf][nf][3]);
                }
            }
        } else if ((g & 1) == 0) {
            // even gate: pack and hold
            #pragma unroll
            for (int mf = 0; mf < 4; mf++)
                #pragma unroll
                for (int nf = 0; nf < 4; nf++) {
                    hold[(mf * 4 + nf) * 2 + 0] = f2h2(acc[mf][nf][0], acc[mf][nf][1]);
                    hold[(mf * 4 + nf) * 2 + 1] = f2h2(acc[mf][nf][2], acc[mf][nf][3]);
                }
        } else {
            // odd gate: merge with held even gate; pair (0,1)->.xy, (2,3)->.zw
            const int zoff = (g & 2) ? 2 : 0;   // uint offset within uint4 word
            uint32_t* __restrict__ P = (uint32_t*)g_P4;
            #pragma unroll
            for (int mf = 0; mf < 4; mf++) {
                int e0 = tile * 128 + wm * 64 + mf * 16 + (lane >> 2);
                #pragma unroll
                for (int nf = 0; nf < 4; nf++) {
                    int d0 = wn * 32 + nf * 8 + (lane & 3) * 2;
                    uint32_t ev0 = hold[(mf * 4 + nf) * 2 + 0];
                    uint32_t ev1 = hold[(mf * 4 + nf) * 2 + 1];
                    uint32_t od0 = f2h2(acc[mf][nf][0], acc[mf][nf][1]);
                    uint32_t od1 = f2h2(acc[mf][nf][2], acc[mf][nf][3]);
                    if (e0 < N_EDGES) {
                        uint2 w = make_uint2(prmt(ev0, od0, 0x5410), prmt(ev0, od0, 0x7632));
                        *(uint2*)&P[(e0 * 64 + (d0 >> 1)) * 4 + zoff] = w;
                    }
                    if (e0 + 8 < N_EDGES) {
                        uint2 w = make_uint2(prmt(ev1, od1, 0x5410), prmt(ev1, od1, 0x7632));
                        *(uint2*)&P[((e0 + 8) * 64 + (d0 >> 1)) * 4 + zoff] = w;
                    }
                }
            }
        }

        if (g + 1 < ngates) {
            CP_WAIT0();
            __syncthreads();   // next buffer ready; all warps done reading current
        }
    }
}

// ---------------------------------------------------------------------------
// Update: per neighbor ONE 16B gather (all 4 gates, 2 dims) + ONE 8B c gather.
// 4 edges per 256-thread block; 64 threads x 2 dims per edge.
// ---------------------------------------------------------------------------
__global__ __launch_bounds__(256) void k_update(
    int cur, int nxt,
    const int* __restrict__ node_ids, const int* __restrict__ edge_src,
    const int* __restrict__ edge_type, const int* __restrict__ bond_list,
    const float* __restrict__ Wi, const float* __restrict__ bi,
    const float* __restrict__ Wo, const float* __restrict__ bo,
    const float* __restrict__ Wf, const float* __restrict__ bf,
    const float* __restrict__ Wu, const float* __restrict__ bu)
{
    __shared__ int s_b[4 * MAX_NB];
    __shared__ int s_nr[4], s_br[4];

    const uint4* __restrict__ P4 = g_P4;
    const float* __restrict__ c_old = g_c[cur];
    float* __restrict__ c_new = g_c[nxt];

    const int tid = threadIdx.x;
    const int e0  = blockIdx.x * 4;

    if (tid < 4 * MAX_NB) {
        s_b[tid] = bond_list[e0 * MAX_NB + tid];
    } else if (tid < 4 * MAX_NB + 4) {
        int e = tid - 4 * MAX_NB;
        s_nr[e] = node_ids[edge_src[e0 + e]];
    } else if (tid < 4 * MAX_NB + 8) {
        int e = tid - 4 * MAX_NB - 4;
        s_br[e] = VOCAB + edge_type[e0 + e];
    }
    __syncthreads();

    const int le = tid >> 6;        // local edge 0..3
    const int dh = tid & 63;        // dim pair index
    const int d0 = dh * 2;
    const int e  = e0 + le;

    int b[MAX_NB];
    #pragma unroll
    for (int k = 0; k < MAX_NB; k++) b[k] = s_b[le * MAX_NB + k];

    // batched independent gathers: 6x16B + 6x8B
    uint4  p[MAX_NB];
    float2 vc[MAX_NB];
    #pragma unroll
    for (int k = 0; k < MAX_NB; k++) {
        p[k]  = P4[b[k] * 64 + dh];
        vc[k] = *(const float2*)&c_old[b[k] * EMB + d0];
    }

    float si[2] = {0.f, 0.f}, so[2] = {0.f, 0.f}, su[2] = {0.f, 0.f};
    float vf[2][MAX_NB];
    #pragma unroll
    for (int k = 0; k < MAX_NB; k++) {
        float2 io0 = __half22float2(*(__half2*)&p[k].x);   // (i,o)@d0
        float2 io1 = __half22float2(*(__half2*)&p[k].y);   // (i,o)@d0+1
        float2 uf0 = __half22float2(*(__half2*)&p[k].z);   // (u,f)@d0
        float2 uf1 = __half22float2(*(__half2*)&p[k].w);   // (u,f)@d0+1
        si[0] += io0.x; so[0] += io0.y; su[0] += uf0.x; vf[0][k] = uf0.y;
        si[1] += io1.x; so[1] += io1.y; su[1] += uf1.x; vf[1][k] = uf1.y;
    }

    const int nr = s_nr[le], br = s_br[le];
    float2 win = *(const float2*)&Wi[nr * EMB + d0];
    float2 wib = *(const float2*)&Wi[br * EMB + d0];
    float2 bi2 = *(const float2*)&bi[d0];
    float2 won = *(const float2*)&Wo[nr * EMB + d0];
    float2 wob = *(const float2*)&Wo[br * EMB + d0];
    float2 bo2 = *(const float2*)&bo[d0];
    float2 wun = *(const float2*)&Wu[nr * EMB + d0];
    float2 wub = *(const float2*)&Wu[br * EMB + d0];
    float2 bu2 = *(const float2*)&bu[d0];
    float2 wfn = *(const float2*)&Wf[nr * EMB + d0];
    float2 wfb = *(const float2*)&Wf[br * EMB + d0];
    float2 bf2 = *(const float2*)&bf[d0];

    float h[2], c[2];
    #pragma unroll
    for (int q = 0; q < 2; q++) {
        float i_g = sigfast(si[q] + (q ? win.y + wib.y + bi2.y : win.x + wib.x + bi2.x));
        float o_g = sigfast(so[q] + (q ? won.y + wob.y + bo2.y : won.x + wob.x + bo2.x));
        float u_g = tanhfast(su[q] + (q ? wun.y + wub.y + bu2.y : wun.x + wub.x + bu2.x));
        float pre_f = (q ? wfn.y + wfb.y + bf2.y : wfn.x + wfb.x + bf2.x);

        float c_acc = i_g * u_g;
        #pragma unroll
        for (int k = 0; k < MAX_NB; k++)
            c_acc += sigfast(vf[q][k] + pre_f) * (q ? vc[k].y : vc[k].x);

        h[q] = o_g * tanhfast(c_acc);
        c[q] = c_acc;
        if (e == 0) { h[q] = 0.f; c[q] = 0.f; }
    }

    *(float2*)&c_new[e * EMB + d0] = make_float2(c[0], c[1]);
    store_h2(nxt, e, d0, h[0], h[1]);
}

// ---------------------------------------------------------------------------
// Final node projection: out = relu(Wt[nid] + bt + sum_k Ht[adj[n,k]])
// ---------------------------------------------------------------------------
__global__ __launch_bounds__(256) void k_final(
    const int* __restrict__ node_ids, const int* __restrict__ adj_list,
    const float* __restrict__ Wt, const float* __restrict__ bt,
    float* __restrict__ out)
{
    __shared__ int s_a[2 * MAX_NB];
    __shared__ int s_nid[2];

    const float* __restrict__ Ht = g_Ht;

    const int tid = threadIdx.x;
    const int n0  = blockIdx.x * 2;

    if (tid < 2 * MAX_NB) {
        s_a[tid] = adj_list[n0 * MAX_NB + tid];
    } else if (tid < 2 * MAX_NB + 2) {
        int n = tid - 2 * MAX_NB;
        s_nid[n] = node_ids[n0 + n];
    }
    __syncthreads();

    const int ln = tid >> 7;
    const int d  = tid & 127;
    const int n  = n0 + ln;

    float s = 0.f;
    #pragma unroll
    for (int k = 0; k < MAX_NB; k++)
        s += Ht[s_a[ln * MAX_NB + k] * EMB + d];

    float v = s + Wt[s_nid[ln] * EMB + d] + bt[d];
    v = fmaxf(v, 0.f);
    if (n == 0) v = 0.f;
    out[n * EMB + d] = v;
}

// ---------------------------------------------------------------------------
extern "C" void kernel_launch(void* const* d_in, const int* in_sizes, int n_in,
                              void* d_out, int out_size)
{
    const int*   node_ids  = (const int*)d_in[0];
    const int*   edge_src  = (const int*)d_in[1];
    const int*   edge_type = (const int*)d_in[2];
    const int*   adj_list  = (const int*)d_in[3];
    const int*   bond_list = (const int*)d_in[4];
    const float* Wi = (const float*)d_in[5];
    const float* bi = (const float*)d_in[6];
    const float* Wo = (const float*)d_in[7];
    const float* bo = (const float*)d_in[8];
    const float* Wf = (const float*)d_in[9];
    const float* bf = (const float*)d_in[10];
    const float* Wu = (const float*)d_in[11];
    const float* bu = (const float*)d_in[12];
    const float* Wt = (const float*)d_in[13];
    const float* bt = (const float*)d_in[14];
    float* out = (float*)d_out;

    cudaFuncSetAttribute(k_mma, cudaFuncAttributeMaxDynamicSharedMemorySize, MMA_SMEM);

    k_prep<<<5, 256>>>(Wi, Wo, Wu, Wf, Wt);
    k_depth0<<<(N_EDGES * 64) / 256, 256>>>(node_ids, edge_src, edge_type,
                                            Wi, bi, Wo, bo, Wu, bu);

    int cur = 0, nxt = 1;
    for (int depth = 1; depth < 4; depth++) {
        k_mma<<<NT, 256, MMA_SMEM>>>(cur, 0, 4);
        k_update<<<N_EDGES / 4, 256>>>(cur, nxt, node_ids, edge_src, edge_type,
                                       bond_list, Wi, bi, Wo, bo, Wf, bf, Wu, bu);
        int t = cur; cur = nxt; nxt = t;
    }

    k_mma<<<NT, 256, MMA_SMEM>>>(cur, 4, 1);   // Ht -> g_Ht (fp32)
    k_final<<<N_NODES / 2, 256>>>(node_ids, adj_list, Wt, bt, out);
}

// round 14
// speedup vs baseline: 6.0896x; 1.1438x over previous
#include <cuda_runtime.h>
#include <cuda_fp16.h>
#include <math.h>
#include <stdint.h>

#define VOCAB   100
#define NBOND   4
#define EMB     128
#define N_NODES 25000
#define N_EDGES 50000
#define MAX_NB  6
#define HOFF    104
#define NT      391              // ceil(50000/128) edge tiles
#define PAD_E   (NT * 128)       // 50048
#define ROWP    136              // padded row length (fp16 elems) -> 272B rows
#define PLANE_A 34816            // 128*ROWP*2 bytes, one 128-row fp16 plane
#define WELEMS  17408            // 128*ROWP elems per W plane

// ---------------- static device scratch (no allocation) ----------------
__device__ float g_c[2][N_EDGES * EMB];                  // cell state ping-pong
// interleaved GEMM gate preacts: per (e, dpair): {io(d), io(d+1), uf(d), uf(d+1)} as 4x half2
__device__ uint4 g_P4[N_EDGES * (EMB / 2)];
// depth-invariant one-hot preacts (incl. biases), same component layout as g_P4
__device__ uint4 g_pre4[N_EDGES * (EMB / 2)];
__device__ float g_Ht[N_EDGES * EMB];                    // final-pass fp32 Ht
__device__ __align__(16) __half g_hb[2][PAD_E * ROWP];   // h fp16 planes (ping-pong), padded rows
__device__ __align__(16) __half g_W[5][WELEMS];          // W[k][d] fp16, padded rows

// fast activations: tanh.approx.f32 (sm_75+ baseline PTX)
__device__ __forceinline__ float tanhfast(float x) {
    float y;
    asm("tanh.approx.f32 %0, %1;" : "=f"(y) : "f"(x));
    return y;
}
__device__ __forceinline__ float sigfast(float x) {
    return fmaf(0.5f, tanhfast(0.5f * x), 0.5f);
}

__device__ __forceinline__ uint32_t smem_u32(const void* p) {
    uint32_t a;
    asm("{ .reg .u64 t; cvta.to.shared.u64 t, %1; cvt.u32.u64 %0, t; }" : "=r"(a) : "l"(p));
    return a;
}
__device__ __forceinline__ void cpa16(uint32_t s, const void* g) {
    asm volatile("cp.async.cg.shared.global [%0], [%1], 16;" :: "r"(s), "l"(g) : "memory");
}
#define CP_COMMIT() asm volatile("cp.async.commit_group;" ::: "memory")
#define CP_WAIT0()  asm volatile("cp.async.wait_group 0;" ::: "memory")

__device__ __forceinline__ void ldsm_x4(uint32_t* r, uint32_t addr) {
    asm volatile("ldmatrix.sync.aligned.m8n8.x4.shared.b16 {%0,%1,%2,%3}, [%4];"
                 : "=r"(r[0]), "=r"(r[1]), "=r"(r[2]), "=r"(r[3]) : "r"(addr));
}
__device__ __forceinline__ void ldsm_x2t(uint32_t* r, uint32_t addr) {
    asm volatile("ldmatrix.sync.aligned.m8n8.x2.trans.shared.b16 {%0,%1}, [%2];"
                 : "=r"(r[0]), "=r"(r[1]) : "r"(addr));
}
// fp16 inputs, fp32 accumulate
__device__ __forceinline__ void mma16816(float* c, const uint32_t* a, const uint32_t* b) {
    asm volatile("mma.sync.aligned.m16n8k16.row.col.f32.f16.f16.f32 "
                 "{%0,%1,%2,%3}, {%4,%5,%6,%7}, {%8,%9}, {%0,%1,%2,%3};"
                 : "+f"(c[0]), "+f"(c[1]), "+f"(c[2]), "+f"(c[3])
                 : "r"(a[0]), "r"(a[1]), "r"(a[2]), "r"(a[3]), "r"(b[0]), "r"(b[1]));
}
__device__ __forceinline__ uint32_t prmt(uint32_t a, uint32_t b, uint32_t s) {
    uint32_t d;
    asm("prmt.b32 %0, %1, %2, %3;" : "=r"(d) : "r"(a), "r"(b), "r"(s));
    return d;
}
__device__ __forceinline__ uint32_t f2h2(float a, float b) {
    __half2 h = __floats2half2_rn(a, b);   // low = a
    return *(uint32_t*)&h;
}

// write (e, d0) and (e, d0+1) h values as one fp16x2 (4B) store
__device__ __forceinline__ void store_h2(int buf, int e, int d0, float h0, float h1) {
    *(uint32_t*)&g_hb[buf][e * ROWP + d0] = f2h2(h0, h1);
}

// ---------------------------------------------------------------------------
// Prep: W fp16 planes, rows k = 0..127 (source rows roff+k), padded to ROWP
// ---------------------------------------------------------------------------
__global__ __launch_bounds__(256) void k_prep(
    const float* __restrict__ Wi, const float* __restrict__ Wo,
    const float* __restrict__ Wu, const float* __restrict__ Wf,
    const float* __restrict__ Wt)
{
    int g = blockIdx.x;
    const float* W;
    int roff;
    switch (g) {
        case 0: W = Wi; roff = HOFF; break;
        case 1: W = Wo; roff = HOFF; break;
        case 2: W = Wu; roff = HOFF; break;
        case 3: W = Wf; roff = HOFF; break;
        default: W = Wt; roff = VOCAB; break;
    }
    for (int idx = threadIdx.x; idx < 16384; idx += 256) {
        int k = idx >> 7;
        int d = idx & 127;
        g_W[g][k * ROWP + d] = __float2half_rn(W[(roff + k) * EMB + d]);
    }
}

// ---------------------------------------------------------------------------
// Depth 0 + precompute: builds depth-invariant one-hot preacts (biases folded)
// for all 4 gates into g_pre4, AND runs the depth-0 update (h=c=0 entering).
// ---------------------------------------------------------------------------
__global__ __launch_bounds__(256) void k_pre0(
    const int* __restrict__ node_ids, const int* __restrict__ edge_src,
    const int* __restrict__ edge_type,
    const float* __restrict__ Wi, const float* __restrict__ bi,
    const float* __restrict__ Wo, const float* __restrict__ bo,
    const float* __restrict__ Wu, const float* __restrict__ bu,
    const float* __restrict__ Wf, const float* __restrict__ bf)
{
    int gidx = blockIdx.x * blockDim.x + threadIdx.x;   // e*64 + dh
    int e = gidx >> 6, dh = gidx & 63;
    int d0 = dh * 2;
    int nrow = node_ids[edge_src[e]];
    int brow = VOCAB + edge_type[e];

    float2 win = *(const float2*)&Wi[nrow * EMB + d0];
    float2 wib = *(const float2*)&Wi[brow * EMB + d0];
    float2 bi2 = *(const float2*)&bi[d0];
    float2 won = *(const float2*)&Wo[nrow * EMB + d0];
    float2 wob = *(const float2*)&Wo[brow * EMB + d0];
    float2 bo2 = *(const float2*)&bo[d0];
    float2 wun = *(const float2*)&Wu[nrow * EMB + d0];
    float2 wub = *(const float2*)&Wu[brow * EMB + d0];
    float2 bu2 = *(const float2*)&bu[d0];
    float2 wfn = *(const float2*)&Wf[nrow * EMB + d0];
    float2 wfb = *(const float2*)&Wf[brow * EMB + d0];
    float2 bf2 = *(const float2*)&bf[d0];

    float pi[2], po[2], pu[2], pf[2];
    pi[0] = win.x + wib.x + bi2.x;  pi[1] = win.y + wib.y + bi2.y;
    po[0] = won.x + wob.x + bo2.x;  po[1] = won.y + wob.y + bo2.y;
    pu[0] = wun.x + wub.x + bu2.x;  pu[1] = wun.y + wub.y + bu2.y;
    pf[0] = wfn.x + wfb.x + bf2.x;  pf[1] = wfn.y + wfb.y + bf2.y;

    // pack depth-invariant preacts: {io(d0), io(d1), uf(d0), uf(d1)}
    uint4 pre;
    pre.x = f2h2(pi[0], po[0]);
    pre.y = f2h2(pi[1], po[1]);
    pre.z = f2h2(pu[0], pf[0]);
    pre.w = f2h2(pu[1], pf[1]);
    g_pre4[e * 64 + dh] = pre;

    // depth-0 update (neighbor sums are zero)
    float h[2], c[2];
    #pragma unroll
    for (int q = 0; q < 2; q++) {
        float i = sigfast(pi[q]), o = sigfast(po[q]), u = tanhfast(pu[q]);
        c[q] = i * u;
        h[q] = o * tanhfast(c[q]);
        if (e == 0) { h[q] = 0.0f; c[q] = 0.0f; }
    }
    *(float2*)&g_c[0][e * EMB + d0] = make_float2(c[0], c[1]);
    store_h2(0, e, d0, h[0], h[1]);
}

// ---------------------------------------------------------------------------
// Tensor-core GEMM via mma.sync fp16 (single term, fp32 accum).
// Gate passes (gbase=0, ngates=4): gates in pairs; even gate held as packed
// halves, merged with the odd gate via prmt into g_P4 components.
// Final pass (gbase=4, ngates=1): fp32 into g_Ht.
// SMEM: A 34KB + 2 W buffers 68KB = 102KB -> 2 CTAs/SM.
// ---------------------------------------------------------------------------
#define MMA_SMEM (3 * PLANE_A)   // 104448 B

__global__ __launch_bounds__(256) void k_mma(int cur, int gbase, int ngates)
{
    extern __shared__ __align__(16) char sm[];
    const int tid  = threadIdx.x;
    const int lane = tid & 31;
    const int wid  = tid >> 5;
    const int wm   = wid >> 2;     // 0..1  -> edge offset wm*64
    const int wn   = wid & 3;      // 0..3  -> dim  offset wn*32
    const int tile = blockIdx.x;

    const uint32_t sA  = smem_u32(sm);
    const uint32_t sB0 = sA + PLANE_A;
    const uint32_t sB1 = sA + 2 * PLANE_A;

    // stage A (h tile) + first W via cp.async
    {
        const uint4* gA = (const uint4*)&g_hb[cur][(size_t)tile * 128 * ROWP];
        const uint4* gW0 = (const uint4*)&g_W[gbase][0];
        for (int i = tid; i < 2176; i += 256) cpa16(sA + i * 16, gA + i);
        for (int i = tid; i < 2176; i += 256) cpa16(sB0 + i * 16, gW0 + i);
        CP_COMMIT();
        CP_WAIT0();
    }
    __syncthreads();

    // per-thread ldmatrix base addresses
    const uint32_t aBase = sA + (uint32_t)((wm * 64 + (lane & 15)) * ROWP + ((lane & 16) ? 8 : 0)) * 2;
    const uint32_t bRow  = (uint32_t)((lane & 15) * ROWP + wn * 32) * 2;

    uint32_t hold[32];   // even gate's halves: per (mf,nf): [d0,d0+1]@e0, [d0,d0+1]@e0+8

    for (int g = 0; g < ngates; g++) {
        // prefetch next gate's W into the other buffer
        if (g + 1 < ngates) {
            const uint4* gw = (const uint4*)&g_W[gbase + g + 1][0];
            uint32_t dst = ((g + 1) & 1) ? sB1 : sB0;
            for (int i = tid; i < 2176; i += 256) cpa16(dst + i * 16, gw + i);
            CP_COMMIT();
        }

        float acc[4][4][4];
        #pragma unroll
        for (int mf = 0; mf < 4; mf++)
            #pragma unroll
            for (int nf = 0; nf < 4; nf++)
                #pragma unroll
                for (int q = 0; q < 4; q++) acc[mf][nf][q] = 0.f;

        const uint32_t sB = ((g & 1) ? sB1 : sB0) + bRow;

        #pragma unroll
        for (int ks = 0; ks < 8; ks++) {
            uint32_t aK = aBase + ks * 32;           // +16 cols * 2B
            uint32_t bK = sB + ks * (16 * ROWP * 2); // +16 k-rows
            uint32_t afr[4][4];
            #pragma unroll
            for (int mf = 0; mf < 4; mf++)
                ldsm_x4(afr[mf], aK + mf * (16 * ROWP * 2));
            uint32_t bfr[4][2];
            #pragma unroll
            for (int nf = 0; nf < 4; nf++)
                ldsm_x2t(bfr[nf], bK + nf * 16);
            #pragma unroll
            for (int mf = 0; mf < 4; mf++)
                #pragma unroll
                for (int nf = 0; nf < 4; nf++)
                    mma16816(acc[mf][nf], afr[mf], bfr[nf]);
        }

        // epilogue
        if (gbase == 4) {
            float* __restrict__ H = g_Ht;
            #pragma unroll
            for (int mf = 0; mf < 4; mf++) {
                int e0 = tile * 128 + wm * 64 + mf * 16 + (lane >> 2);
                #pragma unroll
                for (int nf = 0; nf < 4; nf++) {
                    int d0 = wn * 32 + nf * 8 + (lane & 3) * 2;
                    if (e0 < N_EDGES)
                        *(float2*)&H[e0 * EMB + d0] = make_float2(acc[mf][nf][0], acc[mf][nf][1]);
                    if (e0 + 8 < N_EDGES)
                        *(float2*)&H[(e0 + 8) * EMB + d0] = make_float2(acc[mf][nf][2], acc[mf][nf][3]);
                }
            }
        } else if ((g & 1) == 0) {
            // even gate: pack and hold
            #pragma unroll
            for (int mf = 0; mf < 4; mf++)
                #pragma unroll
                for (int nf = 0; nf < 4; nf++) {
                    hold[(mf * 4 + nf) * 2 + 0] = f2h2(acc[mf][nf][0], acc[mf][nf][1]);
                    hold[(mf * 4 + nf) * 2 + 1] = f2h2(acc[mf][nf][2], acc[mf][nf][3]);
                }
        } else {
            // odd gate: merge with held even gate; pair (0,1)->.xy, (2,3)->.zw
            const int zoff = (g & 2) ? 2 : 0;   // uint offset within uint4 word
            uint32_t* __restrict__ P = (uint32_t*)g_P4;
            #pragma unroll
            for (int mf = 0; mf < 4; mf++) {
                int e0 = tile * 128 + wm * 64 + mf * 16 + (lane >> 2);
                #pragma unroll
                for (int nf = 0; nf < 4; nf++) {
                    int d0 = wn * 32 + nf * 8 + (lane & 3) * 2;
                    uint32_t ev0 = hold[(mf * 4 + nf) * 2 + 0];
                    uint32_t ev1 = hold[(mf * 4 + nf) * 2 + 1];
                    uint32_t od0 = f2h2(acc[mf][nf][0], acc[mf][nf][1]);
                    uint32_t od1 = f2h2(acc[mf][nf][2], acc[mf][nf][3]);
                    if (e0 < N_EDGES) {
                        uint2 w = make_uint2(prmt(ev0, od0, 0x5410), prmt(ev0, od0, 0x7632));
                        *(uint2*)&P[(e0 * 64 + (d0 >> 1)) * 4 + zoff] = w;
                    }
                    if (e0 + 8 < N_EDGES) {
                        uint2 w = make_uint2(prmt(ev1, od1, 0x5410), prmt(ev1, od1, 0x7632));
                        *(uint2*)&P[((e0 + 8) * 64 + (d0 >> 1)) * 4 + zoff] = w;
                    }
                }
            }
        }

        if (g + 1 < ngates) {
            CP_WAIT0();
            __syncthreads();   // next buffer ready; all warps done reading current
        }
    }
}

// ---------------------------------------------------------------------------
// Update: 6x16B P4 gathers + 6x8B c gathers + ONE coalesced 16B pre load.
// 4 edges per 256-thread block; 64 threads x 2 dims per edge.
// ---------------------------------------------------------------------------
__global__ __launch_bounds__(256) void k_update(
    int cur, int nxt, const int* __restrict__ bond_list)
{
    __shared__ int s_b[4 * MAX_NB];

    const uint4* __restrict__ P4 = g_P4;
    const float* __restrict__ c_old = g_c[cur];
    float* __restrict__ c_new = g_c[nxt];

    const int tid = threadIdx.x;
    const int e0  = blockIdx.x * 4;

    if (tid < 4 * MAX_NB)
        s_b[tid] = bond_list[e0 * MAX_NB + tid];
    __syncthreads();

    const int le = tid >> 6;        // local edge 0..3
    const int dh = tid & 63;        // dim pair index
    const int d0 = dh * 2;
    const int e  = e0 + le;

    int b[MAX_NB];
    #pragma unroll
    for (int k = 0; k < MAX_NB; k++) b[k] = s_b[le * MAX_NB + k];

    // batched independent gathers: 6x16B + 6x8B, plus one coalesced pre load
    uint4  p[MAX_NB];
    float2 vc[MAX_NB];
    #pragma unroll
    for (int k = 0; k < MAX_NB; k++) {
        p[k]  = P4[b[k] * 64 + dh];
        vc[k] = *(const float2*)&c_old[b[k] * EMB + d0];
    }
    uint4 pre = g_pre4[e * 64 + dh];

    float si[2] = {0.f, 0.f}, so[2] = {0.f, 0.f}, su[2] = {0.f, 0.f};
    float vf[2][MAX_NB];
    #pragma unroll
    for (int k = 0; k < MAX_NB; k++) {
        float2 io0 = __half22float2(*(__half2*)&p[k].x);   // (i,o)@d0
        float2 io1 = __half22float2(*(__half2*)&p[k].y);   // (i,o)@d0+1
        float2 uf0 = __half22float2(*(__half2*)&p[k].z);   // (u,f)@d0
        float2 uf1 = __half22float2(*(__half2*)&p[k].w);   // (u,f)@d0+1
        si[0] += io0.x; so[0] += io0.y; su[0] += uf0.x; vf[0][k] = uf0.y;
        si[1] += io1.x; so[1] += io1.y; su[1] += uf1.x; vf[1][k] = uf1.y;
    }

    // unpack depth-invariant one-hot preacts (biases included)
    float2 pio0 = __half22float2(*(__half2*)&pre.x);   // (pi,po)@d0
    float2 pio1 = __half22float2(*(__half2*)&pre.y);   // (pi,po)@d0+1
    float2 puf0 = __half22float2(*(__half2*)&pre.z);   // (pu,pf)@d0
    float2 puf1 = __half22float2(*(__half2*)&pre.w);   // (pu,pf)@d0+1

    float h[2], c[2];
    #pragma unroll
    for (int q = 0; q < 2; q++) {
        float pi = q ? pio1.x : pio0.x;
        float po = q ? pio1.y : pio0.y;
        float pu = q ? puf1.x : puf0.x;
        float pf = q ? puf1.y : puf0.y;

        float i_g = sigfast(si[q] + pi);
        float o_g = sigfast(so[q] + po);
        float u_g = tanhfast(su[q] + pu);

        float c_acc = i_g * u_g;
        #pragma unroll
        for (int k = 0; k < MAX_NB; k++)
            c_acc += sigfast(vf[q][k] + pf) * (q ? vc[k].y : vc[k].x);

        h[q] = o_g * tanhfast(c_acc);
        c[q] = c_acc;
        if (e == 0) { h[q] = 0.f; c[q] = 0.f; }
    }

    *(float2*)&c_new[e * EMB + d0] = make_float2(c[0], c[1]);
    store_h2(nxt, e, d0, h[0], h[1]);
}

// ---------------------------------------------------------------------------
// Final node projection: out = relu(Wt[nid] + bt + sum_k Ht[adj[n,k]])
// ---------------------------------------------------------------------------
__global__ __launch_bounds__(256) void k_final(
    const int* __restrict__ node_ids, const int* __restrict__ adj_list,
    const float* __restrict__ Wt, const float* __restrict__ bt,
    float* __restrict__ out)
{
    __shared__ int s_a[2 * MAX_NB];
    __shared__ int s_nid[2];

    const float* __restrict__ Ht = g_Ht;

    const int tid = threadIdx.x;
    const int n0  = blockIdx.x * 2;

    if (tid < 2 * MAX_NB) {
        s_a[tid] = adj_list[n0 * MAX_NB + tid];
    } else if (tid < 2 * MAX_NB + 2) {
        int n = tid - 2 * MAX_NB;
        s_nid[n] = node_ids[n0 + n];
    }
    __syncthreads();

    const int ln = tid >> 7;
    const int d  = tid & 127;
    const int n  = n0 + ln;

    float s = 0.f;
    #pragma unroll
    for (int k = 0; k < MAX_NB; k++)
        s += Ht[s_a[ln * MAX_NB + k] * EMB + d];

    float v = s + Wt[s_nid[ln] * EMB + d] + bt[d];
    v = fmaxf(v, 0.f);
    if (n == 0) v = 0.f;
    out[n * EMB + d] = v;
}

// ---------------------------------------------------------------------------
extern "C" void kernel_launch(void* const* d_in, const int* in_sizes, int n_in,
                              void* d_out, int out_size)
{
    const int*   node_ids  = (const int*)d_in[0];
    const int*   edge_src  = (const int*)d_in[1];
    const int*   edge_type = (const int*)d_in[2];
    const int*   adj_list  = (const int*)d_in[3];
    const int*   bond_list = (const int*)d_in[4];
    const float* Wi = (const float*)d_in[5];
    const float* bi = (const float*)d_in[6];
    const float* Wo = (const float*)d_in[7];
    const float* bo = (const float*)d_in[8];
    const float* Wf = (const float*)d_in[9];
    const float* bf = (const float*)d_in[10];
    const float* Wu = (const float*)d_in[11];
    const float* bu = (const float*)d_in[12];
    const float* Wt = (const float*)d_in[13];
    const float* bt = (const float*)d_in[14];
    float* out = (float*)d_out;

    cudaFuncSetAttribute(k_mma, cudaFuncAttributeMaxDynamicSharedMemorySize, MMA_SMEM);

    k_prep<<<5, 256>>>(Wi, Wo, Wu, Wf, Wt);
    k_pre0<<<(N_EDGES * 64) / 256, 256>>>(node_ids, edge_src, edge_type,
                                          Wi, bi, Wo, bo, Wu, bu, Wf, bf);

    int cur = 0, nxt = 1;
    for (int depth = 1; depth < 4; depth++) {
        k_mma<<<NT, 256, MMA_SMEM>>>(cur, 0, 4);
        k_update<<<N_EDGES / 4, 256>>>(cur, nxt, bond_list);
        int t = cur; cur = nxt; nxt = t;
    }

    k_mma<<<NT, 256, MMA_SMEM>>>(cur, 4, 1);   // Ht -> g_Ht (fp32)
    k_final<<<N_NODES / 2, 256>>>(node_ids, adj_list, Wt, bt, out);
}

// round 15
// speedup vs baseline: 6.7762x; 1.1127x over previous
#include <cuda_runtime.h>
#include <cuda_fp16.h>
#include <math.h>
#include <stdint.h>

#define VOCAB   100
#define NBOND   4
#define EMB     128
#define N_NODES 25000
#define N_EDGES 50000
#define MAX_NB  6
#define HOFF    104
#define NT      391              // ceil(50000/128) edge tiles
#define PAD_E   (NT * 128)       // 50048
#define ROWP    136              // padded row length (fp16 elems) -> 272B rows
#define PLANE_A 34816            // 128*ROWP*2 bytes, one 128-row fp16 plane
#define WELEMS  17408            // 128*ROWP elems per W plane

// ---------------- static device scratch (no allocation) ----------------
// cell state ping-pong, packed fp16: half2(c(d0), c(d0+1)) per (e, dh)
__device__ uint32_t g_ch[2][N_EDGES * (EMB / 2)];
// interleaved GEMM gate preacts: per (e, dpair): {io(d), io(d+1), uf(d), uf(d+1)} as 4x half2
__device__ uint4 g_P4[N_EDGES * (EMB / 2)];
// depth-invariant one-hot preacts (incl. biases), same component layout as g_P4
__device__ uint4 g_pre4[N_EDGES * (EMB / 2)];
__device__ float g_Ht[N_EDGES * EMB];                    // final-pass fp32 Ht
__device__ __align__(16) __half g_hb[2][PAD_E * ROWP];   // h fp16 planes (ping-pong), padded rows
__device__ __align__(16) __half g_W[5][WELEMS];          // W[k][d] fp16, padded rows

// fast activations: tanh.approx.f32 (sm_75+ baseline PTX)
__device__ __forceinline__ float tanhfast(float x) {
    float y;
    asm("tanh.approx.f32 %0, %1;" : "=f"(y) : "f"(x));
    return y;
}
__device__ __forceinline__ float sigfast(float x) {
    return fmaf(0.5f, tanhfast(0.5f * x), 0.5f);
}

__device__ __forceinline__ uint32_t smem_u32(const void* p) {
    uint32_t a;
    asm("{ .reg .u64 t; cvta.to.shared.u64 t, %1; cvt.u32.u64 %0, t; }" : "=r"(a) : "l"(p));
    return a;
}
__device__ __forceinline__ void cpa16(uint32_t s, const void* g) {
    asm volatile("cp.async.cg.shared.global [%0], [%1], 16;" :: "r"(s), "l"(g) : "memory");
}
#define CP_COMMIT() asm volatile("cp.async.commit_group;" ::: "memory")
#define CP_WAIT0()  asm volatile("cp.async.wait_group 0;" ::: "memory")

__device__ __forceinline__ void ldsm_x4(uint32_t* r, uint32_t addr) {
    asm volatile("ldmatrix.sync.aligned.m8n8.x4.shared.b16 {%0,%1,%2,%3}, [%4];"
                 : "=r"(r[0]), "=r"(r[1]), "=r"(r[2]), "=r"(r[3]) : "r"(addr));
}
__device__ __forceinline__ void ldsm_x2t(uint32_t* r, uint32_t addr) {
    asm volatile("ldmatrix.sync.aligned.m8n8.x2.trans.shared.b16 {%0,%1}, [%2];"
                 : "=r"(r[0]), "=r"(r[1]) : "r"(addr));
}
// fp16 inputs, fp32 accumulate
__device__ __forceinline__ void mma16816(float* c, const uint32_t* a, const uint32_t* b) {
    asm volatile("mma.sync.aligned.m16n8k16.row.col.f32.f16.f16.f32 "
                 "{%0,%1,%2,%3}, {%4,%5,%6,%7}, {%8,%9}, {%0,%1,%2,%3};"
                 : "+f"(c[0]), "+f"(c[1]), "+f"(c[2]), "+f"(c[3])
                 : "r"(a[0]), "r"(a[1]), "r"(a[2]), "r"(a[3]), "r"(b[0]), "r"(b[1]));
}
__device__ __forceinline__ uint32_t prmt(uint32_t a, uint32_t b, uint32_t s) {
    uint32_t d;
    asm("prmt.b32 %0, %1, %2, %3;" : "=r"(d) : "r"(a), "r"(b), "r"(s));
    return d;
}
__device__ __forceinline__ uint32_t f2h2(float a, float b) {
    __half2 h = __floats2half2_rn(a, b);   // low = a
    return *(uint32_t*)&h;
}

// write (e, d0) and (e, d0+1) h values as one fp16x2 (4B) store
__device__ __forceinline__ void store_h2(int buf, int e, int d0, float h0, float h1) {
    *(uint32_t*)&g_hb[buf][e * ROWP + d0] = f2h2(h0, h1);
}

// ---------------------------------------------------------------------------
// Prep: W fp16 planes, rows k = 0..127 (source rows roff+k), padded to ROWP
// ---------------------------------------------------------------------------
__global__ __launch_bounds__(256) void k_prep(
    const float* __restrict__ Wi, const float* __restrict__ Wo,
    const float* __restrict__ Wu, const float* __restrict__ Wf,
    const float* __restrict__ Wt)
{
    int g = blockIdx.x;
    const float* W;
    int roff;
    switch (g) {
        case 0: W = Wi; roff = HOFF; break;
        case 1: W = Wo; roff = HOFF; break;
        case 2: W = Wu; roff = HOFF; break;
        case 3: W = Wf; roff = HOFF; break;
        default: W = Wt; roff = VOCAB; break;
    }
    for (int idx = threadIdx.x; idx < 16384; idx += 256) {
        int k = idx >> 7;
        int d = idx & 127;
        g_W[g][k * ROWP + d] = __float2half_rn(W[(roff + k) * EMB + d]);
    }
}

// ---------------------------------------------------------------------------
// Depth 0 + precompute: builds depth-invariant one-hot preacts (biases folded)
// for all 4 gates into g_pre4, AND runs the depth-0 update (h=c=0 entering).
// ---------------------------------------------------------------------------
__global__ __launch_bounds__(256) void k_pre0(
    const int* __restrict__ node_ids, const int* __restrict__ edge_src,
    const int* __restrict__ edge_type,
    const float* __restrict__ Wi, const float* __restrict__ bi,
    const float* __restrict__ Wo, const float* __restrict__ bo,
    const float* __restrict__ Wu, const float* __restrict__ bu,
    const float* __restrict__ Wf, const float* __restrict__ bf)
{
    int gidx = blockIdx.x * blockDim.x + threadIdx.x;   // e*64 + dh
    int e = gidx >> 6, dh = gidx & 63;
    int d0 = dh * 2;
    int nrow = node_ids[edge_src[e]];
    int brow = VOCAB + edge_type[e];

    float2 win = *(const float2*)&Wi[nrow * EMB + d0];
    float2 wib = *(const float2*)&Wi[brow * EMB + d0];
    float2 bi2 = *(const float2*)&bi[d0];
    float2 won = *(const float2*)&Wo[nrow * EMB + d0];
    float2 wob = *(const float2*)&Wo[brow * EMB + d0];
    float2 bo2 = *(const float2*)&bo[d0];
    float2 wun = *(const float2*)&Wu[nrow * EMB + d0];
    float2 wub = *(const float2*)&Wu[brow * EMB + d0];
    float2 bu2 = *(const float2*)&bu[d0];
    float2 wfn = *(const float2*)&Wf[nrow * EMB + d0];
    float2 wfb = *(const float2*)&Wf[brow * EMB + d0];
    float2 bf2 = *(const float2*)&bf[d0];

    float pi[2], po[2], pu[2], pf[2];
    pi[0] = win.x + wib.x + bi2.x;  pi[1] = win.y + wib.y + bi2.y;
    po[0] = won.x + wob.x + bo2.x;  po[1] = won.y + wob.y + bo2.y;
    pu[0] = wun.x + wub.x + bu2.x;  pu[1] = wun.y + wub.y + bu2.y;
    pf[0] = wfn.x + wfb.x + bf2.x;  pf[1] = wfn.y + wfb.y + bf2.y;

    // pack depth-invariant preacts: {io(d0), io(d1), uf(d0), uf(d1)}
    uint4 pre;
    pre.x = f2h2(pi[0], po[0]);
    pre.y = f2h2(pi[1], po[1]);
    pre.z = f2h2(pu[0], pf[0]);
    pre.w = f2h2(pu[1], pf[1]);
    g_pre4[e * 64 + dh] = pre;

    // depth-0 update (neighbor sums are zero)
    float h[2], c[2];
    #pragma unroll
    for (int q = 0; q < 2; q++) {
        float i = sigfast(pi[q]), o = sigfast(po[q]), u = tanhfast(pu[q]);
        c[q] = i * u;
        h[q] = o * tanhfast(c[q]);
        if (e == 0) { h[q] = 0.0f; c[q] = 0.0f; }
    }
    g_ch[0][e * 64 + dh] = f2h2(c[0], c[1]);
    store_h2(0, e, d0, h[0], h[1]);
}

// ---------------------------------------------------------------------------
// Tensor-core GEMM via mma.sync fp16 (single term, fp32 accum).
// Gate passes (gbase=0, ngates=4): gates in pairs; even gate held as packed
// halves, merged with the odd gate via prmt into g_P4 components.
// Final pass (gbase=4, ngates=1): fp32 into g_Ht.
// SMEM: A 34KB + 2 W buffers 68KB = 102KB -> 2 CTAs/SM.
// ---------------------------------------------------------------------------
#define MMA_SMEM (3 * PLANE_A)   // 104448 B

__global__ __launch_bounds__(256) void k_mma(int cur, int gbase, int ngates)
{
    extern __shared__ __align__(16) char sm[];
    const int tid  = threadIdx.x;
    const int lane = tid & 31;
    const int wid  = tid >> 5;
    const int wm   = wid >> 2;     // 0..1  -> edge offset wm*64
    const int wn   = wid & 3;      // 0..3  -> dim  offset wn*32
    const int tile = blockIdx.x;

    const uint32_t sA  = smem_u32(sm);
    const uint32_t sB0 = sA + PLANE_A;
    const uint32_t sB1 = sA + 2 * PLANE_A;

    // stage A (h tile) + first W via cp.async
    {
        const uint4* gA = (const uint4*)&g_hb[cur][(size_t)tile * 128 * ROWP];
        const uint4* gW0 = (const uint4*)&g_W[gbase][0];
        for (int i = tid; i < 2176; i += 256) cpa16(sA + i * 16, gA + i);
        for (int i = tid; i < 2176; i += 256) cpa16(sB0 + i * 16, gW0 + i);
        CP_COMMIT();
        CP_WAIT0();
    }
    __syncthreads();

    // per-thread ldmatrix base addresses
    const uint32_t aBase = sA + (uint32_t)((wm * 64 + (lane & 15)) * ROWP + ((lane & 16) ? 8 : 0)) * 2;
    const uint32_t bRow  = (uint32_t)((lane & 15) * ROWP + wn * 32) * 2;

    uint32_t hold[32];   // even gate's halves: per (mf,nf): [d0,d0+1]@e0, [d0,d0+1]@e0+8

    for (int g = 0; g < ngates; g++) {
        // prefetch next gate's W into the other buffer
        if (g + 1 < ngates) {
            const uint4* gw = (const uint4*)&g_W[gbase + g + 1][0];
            uint32_t dst = ((g + 1) & 1) ? sB1 : sB0;
            for (int i = tid; i < 2176; i += 256) cpa16(dst + i * 16, gw + i);
            CP_COMMIT();
        }

        float acc[4][4][4];
        #pragma unroll
        for (int mf = 0; mf < 4; mf++)
            #pragma unroll
            for (int nf = 0; nf < 4; nf++)
                #pragma unroll
                for (int q = 0; q < 4; q++) acc[mf][nf][q] = 0.f;

        const uint32_t sB = ((g & 1) ? sB1 : sB0) + bRow;

        #pragma unroll
        for (int ks = 0; ks < 8; ks++) {
            uint32_t aK = aBase + ks * 32;           // +16 cols * 2B
            uint32_t bK = sB + ks * (16 * ROWP * 2); // +16 k-rows
            uint32_t afr[4][4];
            #pragma unroll
            for (int mf = 0; mf < 4; mf++)
                ldsm_x4(afr[mf], aK + mf * (16 * ROWP * 2));
            uint32_t bfr[4][2];
            #pragma unroll
            for (int nf = 0; nf < 4; nf++)
                ldsm_x2t(bfr[nf], bK + nf * 16);
            #pragma unroll
            for (int mf = 0; mf < 4; mf++)
                #pragma unroll
                for (int nf = 0; nf < 4; nf++)
                    mma16816(acc[mf][nf], afr[mf], bfr[nf]);
        }

        // epilogue
        if (gbase == 4) {
            float* __restrict__ H = g_Ht;
            #pragma unroll
            for (int mf = 0; mf < 4; mf++) {
                int e0 = tile * 128 + wm * 64 + mf * 16 + (lane >> 2);
                #pragma unroll
                for (int nf = 0; nf < 4; nf++) {
                    int d0 = wn * 32 + nf * 8 + (lane & 3) * 2;
                    if (e0 < N_EDGES)
                        *(float2*)&H[e0 * EMB + d0] = make_float2(acc[mf][nf][0], acc[mf][nf][1]);
                    if (e0 + 8 < N_EDGES)
                        *(float2*)&H[(e0 + 8) * EMB + d0] = make_float2(acc[mf][nf][2], acc[mf][nf][3]);
                }
            }
        } else if ((g & 1) == 0) {
            // even gate: pack and hold
            #pragma unroll
            for (int mf = 0; mf < 4; mf++)
                #pragma unroll
                for (int nf = 0; nf < 4; nf++) {
                    hold[(mf * 4 + nf) * 2 + 0] = f2h2(acc[mf][nf][0], acc[mf][nf][1]);
                    hold[(mf * 4 + nf) * 2 + 1] = f2h2(acc[mf][nf][2], acc[mf][nf][3]);
                }
        } else {
            // odd gate: merge with held even gate; pair (0,1)->.xy, (2,3)->.zw
            const int zoff = (g & 2) ? 2 : 0;   // uint offset within uint4 word
            uint32_t* __restrict__ P = (uint32_t*)g_P4;
            #pragma unroll
            for (int mf = 0; mf < 4; mf++) {
                int e0 = tile * 128 + wm * 64 + mf * 16 + (lane >> 2);
                #pragma unroll
                for (int nf = 0; nf < 4; nf++) {
                    int d0 = wn * 32 + nf * 8 + (lane & 3) * 2;
                    uint32_t ev0 = hold[(mf * 4 + nf) * 2 + 0];
                    uint32_t ev1 = hold[(mf * 4 + nf) * 2 + 1];
                    uint32_t od0 = f2h2(acc[mf][nf][0], acc[mf][nf][1]);
                    uint32_t od1 = f2h2(acc[mf][nf][2], acc[mf][nf][3]);
                    if (e0 < N_EDGES) {
                        uint2 w = make_uint2(prmt(ev0, od0, 0x5410), prmt(ev0, od0, 0x7632));
                        *(uint2*)&P[(e0 * 64 + (d0 >> 1)) * 4 + zoff] = w;
                    }
                    if (e0 + 8 < N_EDGES) {
                        uint2 w = make_uint2(prmt(ev1, od1, 0x5410), prmt(ev1, od1, 0x7632));
                        *(uint2*)&P[((e0 + 8) * 64 + (d0 >> 1)) * 4 + zoff] = w;
                    }
                }
            }
        }

        if (g + 1 < ngates) {
            CP_WAIT0();
            __syncthreads();   // next buffer ready; all warps done reading current
        }
    }
}

// ---------------------------------------------------------------------------
// Update: 6x16B P4 gathers + 6x4B fp16 c gathers + ONE streamed 16B pre load.
// 4 edges per 256-thread block; 64 threads x 2 dims per edge.
// ---------------------------------------------------------------------------
__global__ __launch_bounds__(256) void k_update(
    int cur, int nxt, const int* __restrict__ bond_list)
{
    __shared__ int s_b[4 * MAX_NB];

    const uint4* __restrict__ P4 = g_P4;
    const uint32_t* __restrict__ c_old = g_ch[cur];
    uint32_t* __restrict__ c_new = g_ch[nxt];

    const int tid = threadIdx.x;
    const int e0  = blockIdx.x * 4;

    if (tid < 4 * MAX_NB)
        s_b[tid] = bond_list[e0 * MAX_NB + tid];
    __syncthreads();

    const int le = tid >> 6;        // local edge 0..3
    const int dh = tid & 63;        // dim pair index
    const int d0 = dh * 2;
    const int e  = e0 + le;

    int b[MAX_NB];
    #pragma unroll
    for (int k = 0; k < MAX_NB; k++) b[k] = s_b[le * MAX_NB + k];

    // batched independent gathers: 6x16B + 6x4B, plus one streamed pre load
    uint4    p[MAX_NB];
    uint32_t cw[MAX_NB];
    #pragma unroll
    for (int k = 0; k < MAX_NB; k++) {
        p[k]  = P4[b[k] * 64 + dh];
        cw[k] = c_old[b[k] * 64 + dh];
    }
    uint4 pre = __ldcs(&g_pre4[e * 64 + dh]);   // evict-first: protect gather set

    float si[2] = {0.f, 0.f}, so[2] = {0.f, 0.f}, su[2] = {0.f, 0.f};
    float vf[2][MAX_NB];
    float2 vc[MAX_NB];
    #pragma unroll
    for (int k = 0; k < MAX_NB; k++) {
        float2 io0 = __half22float2(*(__half2*)&p[k].x);   // (i,o)@d0
        float2 io1 = __half22float2(*(__half2*)&p[k].y);   // (i,o)@d0+1
        float2 uf0 = __half22float2(*(__half2*)&p[k].z);   // (u,f)@d0
        float2 uf1 = __half22float2(*(__half2*)&p[k].w);   // (u,f)@d0+1
        si[0] += io0.x; so[0] += io0.y; su[0] += uf0.x; vf[0][k] = uf0.y;
        si[1] += io1.x; so[1] += io1.y; su[1] += uf1.x; vf[1][k] = uf1.y;
        vc[k] = __half22float2(*(__half2*)&cw[k]);         // (c(d0), c(d0+1))
    }

    // unpack depth-invariant one-hot preacts (biases included)
    float2 pio0 = __half22float2(*(__half2*)&pre.x);   // (pi,po)@d0
    float2 pio1 = __half22float2(*(__half2*)&pre.y);   // (pi,po)@d0+1
    float2 puf0 = __half22float2(*(__half2*)&pre.z);   // (pu,pf)@d0
    float2 puf1 = __half22float2(*(__half2*)&pre.w);   // (pu,pf)@d0+1

    float h[2], c[2];
    #pragma unroll
    for (int q = 0; q < 2; q++) {
        float pi = q ? pio1.x : pio0.x;
        float po = q ? pio1.y : pio0.y;
        float pu = q ? puf1.x : puf0.x;
        float pf = q ? puf1.y : puf0.y;

        float i_g = sigfast(si[q] + pi);
        float o_g = sigfast(so[q] + po);
        float u_g = tanhfast(su[q] + pu);

        float c_acc = i_g * u_g;
        #pragma unroll
        for (int k = 0; k < MAX_NB; k++)
            c_acc += sigfast(vf[q][k] + pf) * (q ? vc[k].y : vc[k].x);

        h[q] = o_g * tanhfast(c_acc);
        c[q] = c_acc;
        if (e == 0) { h[q] = 0.f; c[q] = 0.f; }
    }

    c_new[e * 64 + dh] = f2h2(c[0], c[1]);
    store_h2(nxt, e, d0, h[0], h[1]);
}

// ---------------------------------------------------------------------------
// Final node projection: out = relu(Wt[nid] + bt + sum_k Ht[adj[n,k]])
// ---------------------------------------------------------------------------
__global__ __launch_bounds__(256) void k_final(
    const int* __restrict__ node_ids, const int* __restrict__ adj_list,
    const float* __restrict__ Wt, const float* __restrict__ bt,
    float* __restrict__ out)
{
    __shared__ int s_a[2 * MAX_NB];
    __shared__ int s_nid[2];

    const float* __restrict__ Ht = g_Ht;

    const int tid = threadIdx.x;
    const int n0  = blockIdx.x * 2;

    if (tid < 2 * MAX_NB) {
        s_a[tid] = adj_list[n0 * MAX_NB + tid];
    } else if (tid < 2 * MAX_NB + 2) {
        int n = tid - 2 * MAX_NB;
        s_nid[n] = node_ids[n0 + n];
    }
    __syncthreads();

    const int ln = tid >> 7;
    const int d  = tid & 127;
    const int n  = n0 + ln;

    float s = 0.f;
    #pragma unroll
    for (int k = 0; k < MAX_NB; k++)
        s += Ht[s_a[ln * MAX_NB + k] * EMB + d];

    float v = s + Wt[s_nid[ln] * EMB + d] + bt[d];
    v = fmaxf(v, 0.f);
    if (n == 0) v = 0.f;
    out[n * EMB + d] = v;
}

// ---------------------------------------------------------------------------
extern "C" void kernel_launch(void* const* d_in, const int* in_sizes, int n_in,
                              void* d_out, int out_size)
{
    const int*   node_ids  = (const int*)d_in[0];
    const int*   edge_src  = (const int*)d_in[1];
    const int*   edge_type = (const int*)d_in[2];
    const int*   adj_list  = (const int*)d_in[3];
    const int*   bond_list = (const int*)d_in[4];
    const float* Wi = (const float*)d_in[5];
    const float* bi = (const float*)d_in[6];
    const float* Wo = (const float*)d_in[7];
    const float* bo = (const float*)d_in[8];
    const float* Wf = (const float*)d_in[9];
    const float* bf = (const float*)d_in[10];
    const float* Wu = (const float*)d_in[11];
    const float* bu = (const float*)d_in[12];
    const float* Wt = (const float*)d_in[13];
    const float* bt = (const float*)d_in[14];
    float* out = (float*)d_out;

    cudaFuncSetAttribute(k_mma, cudaFuncAttributeMaxDynamicSharedMemorySize, MMA_SMEM);

    k_prep<<<5, 256>>>(Wi, Wo, Wu, Wf, Wt);
    k_pre0<<<(N_EDGES * 64) / 256, 256>>>(node_ids, edge_src, edge_type,
                                          Wi, bi, Wo, bo, Wu, bu, Wf, bf);

    int cur = 0, nxt = 1;
    for (int depth = 1; depth < 4; depth++) {
        k_mma<<<NT, 256, MMA_SMEM>>>(cur, 0, 4);
        k_update<<<N_EDGES / 4, 256>>>(cur, nxt, bond_list);
        int t = cur; cur = nxt; nxt = t;
    }

    k_mma<<<NT, 256, MMA_SMEM>>>(cur, 4, 1);   // Ht -> g_Ht (fp32)
    k_final<<<N_NODES / 2, 256>>>(node_ids, adj_list, Wt, bt, out);
}